// round 2
// baseline (speedup 1.0000x reference)
#include <cuda_runtime.h>

// Problem constants
#define Tn   2048
#define Dn   1024
#define Hn   16
#define HDn  64
#define Bn   2
#define ROWS (Bn * Tn)   // 4096

// ---------------- scratch (static device globals; no allocations) ----------
__device__ float g_h1 [ROWS * Dn];                    // LN1 output
__device__ float g_q  [Bn * Hn * Tn * HDn];
__device__ float g_k  [Bn * Hn * Tn * HDn];
__device__ float g_v  [Bn * Hn * Tn * HDn];
__device__ float g_sc [(long long)Bn * Hn * Tn * Tn]; // 536 MB scores/attn
__device__ float g_att[ROWS * Dn];                    // concat(heads) attn out
__device__ float g_x2 [ROWS * Dn];                    // residual after attn
__device__ float g_h2 [ROWS * Dn];                    // LN2 output
__device__ float g_mid[ROWS * 4 * Dn];                // FFN hidden

// ---------------------------------------------------------------------------
// Generic batched SGEMM: C = alpha * A @ B(^T) [+ bias] [+ relu] [+ res]
//   EPI: 0 = none, 1 = bias+relu, 2 = bias+residual
// Batch offsets: ptr += (z/div)*stride1 + (z%mod)*stride2  for A, B, C.
// Assumes M%128==0, N%64==0, K%16==0 (true for all shapes here).
// ---------------------------------------------------------------------------
template <bool TRANSB, int EPI>
__launch_bounds__(256)
__global__ void gemm_kernel(const float* __restrict__ A,
                            const float* __restrict__ B,
                            float* __restrict__ C,
                            const float* __restrict__ bias,
                            const float* __restrict__ res,
                            int M, int N, int K,
                            int lda, int ldb, int ldc, float alpha,
                            long long sA1, int dA, long long sA2, int mA,
                            long long sB1, int dB, long long sB2, int mB,
                            long long sC1, int dC, long long sC2, int mC)
{
    constexpr int BM = 128, BN = 64, BK = 16;
    __shared__ float As[BK][BM + 4];   // +4: keeps float4 alignment, breaks bank conflicts
    __shared__ float Bs[BK][BN + 4];

    const int z = blockIdx.z;
    A += (long long)(z / dA) * sA1 + (long long)(z % mA) * sA2;
    B += (long long)(z / dB) * sB1 + (long long)(z % mB) * sB2;
    const long long coff = (long long)(z / dC) * sC1 + (long long)(z % mC) * sC2;
    C += coff;
    if (EPI == 2) res += coff;

    const int tid = threadIdx.x;
    const int tx = tid & 15;        // 16 col-groups of 4
    const int ty = tid >> 4;        // 16 row-groups of 8
    const int m0 = blockIdx.y * BM;
    const int n0 = blockIdx.x * BN;

    float acc[8][4];
#pragma unroll
    for (int i = 0; i < 8; i++)
#pragma unroll
        for (int j = 0; j < 4; j++) acc[i][j] = 0.f;

    for (int k0 = 0; k0 < K; k0 += BK) {
        // ---- load A tile (128x16) as float4, transpose into As[k][m]
#pragma unroll
        for (int l = 0; l < 2; l++) {
            int idx = tid + l * 256;          // 0..511
            int mm  = idx >> 2;               // 0..127
            int kk4 = idx & 3;                // 0..3
            float4 va = *reinterpret_cast<const float4*>(
                &A[(long long)(m0 + mm) * lda + k0 + kk4 * 4]);
            As[kk4 * 4 + 0][mm] = va.x;
            As[kk4 * 4 + 1][mm] = va.y;
            As[kk4 * 4 + 2][mm] = va.z;
            As[kk4 * 4 + 3][mm] = va.w;
        }
        // ---- load B tile (16x64)
        if (TRANSB) {                          // B is [N,K] row-major
            int kk4 = tid & 3;                 // 0..3
            int nn  = tid >> 2;                // 0..63
            float4 vb = *reinterpret_cast<const float4*>(
                &B[(long long)(n0 + nn) * ldb + k0 + kk4 * 4]);
            Bs[kk4 * 4 + 0][nn] = vb.x;
            Bs[kk4 * 4 + 1][nn] = vb.y;
            Bs[kk4 * 4 + 2][nn] = vb.z;
            Bs[kk4 * 4 + 3][nn] = vb.w;
        } else {                               // B is [K,N] row-major
            int nn4 = tid & 15;                // 0..15
            int kk  = tid >> 4;                // 0..15
            float4 vb = *reinterpret_cast<const float4*>(
                &B[(long long)(k0 + kk) * ldb + n0 + nn4 * 4]);
            *reinterpret_cast<float4*>(&Bs[kk][nn4 * 4]) = vb;
        }
        __syncthreads();

#pragma unroll
        for (int kk = 0; kk < BK; kk++) {
            float4 a0 = *reinterpret_cast<const float4*>(&As[kk][ty * 8]);
            float4 a1 = *reinterpret_cast<const float4*>(&As[kk][ty * 8 + 4]);
            float4 b0 = *reinterpret_cast<const float4*>(&Bs[kk][tx * 4]);
            float a[8] = {a0.x, a0.y, a0.z, a0.w, a1.x, a1.y, a1.z, a1.w};
            float b[4] = {b0.x, b0.y, b0.z, b0.w};
#pragma unroll
            for (int i = 0; i < 8; i++)
#pragma unroll
                for (int j = 0; j < 4; j++)
                    acc[i][j] = fmaf(a[i], b[j], acc[i][j]);
        }
        __syncthreads();
    }

    // ---- epilogue
    float4 bv = make_float4(0.f, 0.f, 0.f, 0.f);
    if (EPI >= 1) bv = *reinterpret_cast<const float4*>(&bias[n0 + tx * 4]);

#pragma unroll
    for (int i = 0; i < 8; i++) {
        long long row = m0 + ty * 8 + i;
        int col = n0 + tx * 4;
        float4 v;
        v.x = acc[i][0] * alpha;
        v.y = acc[i][1] * alpha;
        v.z = acc[i][2] * alpha;
        v.w = acc[i][3] * alpha;
        if (EPI >= 1) { v.x += bv.x; v.y += bv.y; v.z += bv.z; v.w += bv.w; }
        if (EPI == 1) {
            v.x = fmaxf(v.x, 0.f); v.y = fmaxf(v.y, 0.f);
            v.z = fmaxf(v.z, 0.f); v.w = fmaxf(v.w, 0.f);
        }
        if (EPI == 2) {
            float4 r = *reinterpret_cast<const float4*>(&res[row * ldc + col]);
            v.x += r.x; v.y += r.y; v.z += r.z; v.w += r.w;
        }
        *reinterpret_cast<float4*>(&C[row * ldc + col]) = v;
    }
}

// ---------------------------------------------------------------------------
// LayerNorm over last dim (1024). One block (256 threads) per row.
// ---------------------------------------------------------------------------
__launch_bounds__(256)
__global__ void ln_kernel(const float* __restrict__ x,
                          const float* __restrict__ g,
                          const float* __restrict__ be,
                          float* __restrict__ out)
{
    long long row = blockIdx.x;
    const float* xr = x + row * Dn;
    float* outr = out + row * Dn;
    int tid = threadIdx.x;

    float v[4];
    float s = 0.f;
#pragma unroll
    for (int i = 0; i < 4; i++) { v[i] = xr[tid + 256 * i]; s += v[i]; }

    __shared__ float red[8];
    __shared__ float sh_mu, sh_rstd;

#pragma unroll
    for (int o = 16; o > 0; o >>= 1) s += __shfl_xor_sync(0xffffffffu, s, o);
    if ((tid & 31) == 0) red[tid >> 5] = s;
    __syncthreads();
    if (tid == 0) {
        float t = 0.f;
        for (int i = 0; i < 8; i++) t += red[i];
        sh_mu = t * (1.0f / Dn);
    }
    __syncthreads();
    float mu = sh_mu;

    float ss = 0.f;
#pragma unroll
    for (int i = 0; i < 4; i++) { float d = v[i] - mu; ss += d * d; }
#pragma unroll
    for (int o = 16; o > 0; o >>= 1) ss += __shfl_xor_sync(0xffffffffu, ss, o);
    if ((tid & 31) == 0) red[tid >> 5] = ss;
    __syncthreads();
    if (tid == 0) {
        float t = 0.f;
        for (int i = 0; i < 8; i++) t += red[i];
        sh_rstd = rsqrtf(t * (1.0f / Dn) + 1e-5f);
    }
    __syncthreads();
    float rstd = sh_rstd;

#pragma unroll
    for (int i = 0; i < 4; i++) {
        int c = tid + 256 * i;
        outr[c] = (v[i] - mu) * rstd * g[c] + be[c];
    }
}

// ---------------------------------------------------------------------------
// In-place causal softmax on scores [B*H, T, T]. One block per row.
// Entries beyond the causal boundary are written as 0 (so PV GEMM over full K works).
// ---------------------------------------------------------------------------
__launch_bounds__(256)
__global__ void softmax_kernel(float* __restrict__ S)
{
    long long row = blockIdx.x;              // 0 .. B*H*T-1
    int t = (int)(row & (Tn - 1));
    float* p = S + row * Tn;
    int n = t + 1;
    int tid = threadIdx.x;

    __shared__ float red[8];
    __shared__ float sh;

    float mx = -3.4e38f;
    for (int i = tid; i < n; i += 256) mx = fmaxf(mx, p[i]);
#pragma unroll
    for (int o = 16; o > 0; o >>= 1) mx = fmaxf(mx, __shfl_xor_sync(0xffffffffu, mx, o));
    if ((tid & 31) == 0) red[tid >> 5] = mx;
    __syncthreads();
    if (tid == 0) {
        float t2 = red[0];
        for (int i = 1; i < 8; i++) t2 = fmaxf(t2, red[i]);
        sh = t2;
    }
    __syncthreads();
    mx = sh;

    float s = 0.f;
    for (int i = tid; i < n; i += 256) s += expf(p[i] - mx);
#pragma unroll
    for (int o = 16; o > 0; o >>= 1) s += __shfl_xor_sync(0xffffffffu, s, o);
    if ((tid & 31) == 0) red[tid >> 5] = s;
    __syncthreads();
    if (tid == 0) {
        float t2 = 0.f;
        for (int i = 0; i < 8; i++) t2 += red[i];
        sh = 1.0f / t2;
    }
    __syncthreads();
    float inv = sh;

    for (int i = tid; i < Tn; i += 256)
        p[i] = (i < n) ? expf(p[i] - mx) * inv : 0.0f;
}

// ---------------------------------------------------------------------------
extern "C" void kernel_launch(void* const* d_in, const int* in_sizes, int n_in,
                              void* d_out, int out_size)
{
    const float* x   = (const float*)d_in[0];
    const float* Wq  = (const float*)d_in[1];
    const float* Wk  = (const float*)d_in[2];
    const float* Wv  = (const float*)d_in[3];
    const float* Wo  = (const float*)d_in[4];
    const float* bo  = (const float*)d_in[5];
    const float* W1  = (const float*)d_in[6];
    const float* b1  = (const float*)d_in[7];
    const float* W2  = (const float*)d_in[8];
    const float* b2  = (const float*)d_in[9];
    const float* g1  = (const float*)d_in[10];
    const float* be1 = (const float*)d_in[11];
    const float* g2  = (const float*)d_in[12];
    const float* be2 = (const float*)d_in[13];
    float* out = (float*)d_out;

    float *h1, *q, *k, *v, *sc, *att, *x2, *h2, *mid;
    cudaGetSymbolAddress((void**)&h1,  g_h1);
    cudaGetSymbolAddress((void**)&q,   g_q);
    cudaGetSymbolAddress((void**)&k,   g_k);
    cudaGetSymbolAddress((void**)&v,   g_v);
    cudaGetSymbolAddress((void**)&sc,  g_sc);
    cudaGetSymbolAddress((void**)&att, g_att);
    cudaGetSymbolAddress((void**)&x2,  g_x2);
    cudaGetSymbolAddress((void**)&h2,  g_h2);
    cudaGetSymbolAddress((void**)&mid, g_mid);

    dim3 blk(256);

    // LN1: x -> h1
    ln_kernel<<<ROWS, blk>>>(x, g1, be1, h1);

    // QKV projections: per (b,h) GEMM [T,D]x[D,HD]; z = b*H + h
    {
        dim3 grd(HDn / 64, Tn / 128, Bn * Hn);
        const long long sA = (long long)Tn * Dn;   // per-batch (z/H)
        const long long sB = (long long)Dn * HDn;  // per-head  (z%H)
        const long long sC = (long long)Tn * HDn;  // per z
        gemm_kernel<false, 0><<<grd, blk>>>(h1, Wq, q, nullptr, nullptr,
            Tn, HDn, Dn, Dn, HDn, HDn, 1.0f,
            sA, Hn, 0LL, 1,   0LL, 1, sB, Hn,   sC, 1, 0LL, 1);
        gemm_kernel<false, 0><<<grd, blk>>>(h1, Wk, k, nullptr, nullptr,
            Tn, HDn, Dn, Dn, HDn, HDn, 1.0f,
            sA, Hn, 0LL, 1,   0LL, 1, sB, Hn,   sC, 1, 0LL, 1);
        gemm_kernel<false, 0><<<grd, blk>>>(h1, Wv, v, nullptr, nullptr,
            Tn, HDn, Dn, Dn, HDn, HDn, 1.0f,
            sA, Hn, 0LL, 1,   0LL, 1, sB, Hn,   sC, 1, 0LL, 1);
    }

    // scores = (Q @ K^T) * D^-0.5  (per z)
    {
        dim3 grd(Tn / 64, Tn / 128, Bn * Hn);
        const long long sQK = (long long)Tn * HDn;
        const long long sS  = (long long)Tn * Tn;
        gemm_kernel<true, 0><<<grd, blk>>>(q, k, sc, nullptr, nullptr,
            Tn, Tn, HDn, HDn, HDn, Tn, 0.03125f,
            sQK, 1, 0LL, 1,   sQK, 1, 0LL, 1,   sS, 1, 0LL, 1);
    }

    // causal softmax in place
    softmax_kernel<<<Bn * Hn * Tn, blk>>>(sc);

    // attn @ V -> att in concat layout [B,T, h*HD+e]
    {
        dim3 grd(HDn / 64, Tn / 128, Bn * Hn);
        const long long sS = (long long)Tn * Tn;
        const long long sV = (long long)Tn * HDn;
        gemm_kernel<false, 0><<<grd, blk>>>(sc, v, att, nullptr, nullptr,
            Tn, HDn, Tn, Tn, HDn, Dn, 1.0f,
            sS, 1, 0LL, 1,   sV, 1, 0LL, 1,
            (long long)Tn * Dn, Hn, (long long)HDn, Hn);
    }

    // O projection + bias + residual: x2 = x + att @ Wo + bo
    {
        dim3 grd(Dn / 64, ROWS / 128, 1);
        gemm_kernel<false, 2><<<grd, blk>>>(att, Wo, x2, bo, x,
            ROWS, Dn, Dn, Dn, Dn, Dn, 1.0f,
            0LL, 1, 0LL, 1,   0LL, 1, 0LL, 1,   0LL, 1, 0LL, 1);
    }

    // LN2: x2 -> h2
    ln_kernel<<<ROWS, blk>>>(x2, g2, be2, h2);

    // FFN1: mid = relu(h2 @ W1 + b1)
    {
        dim3 grd(4 * Dn / 64, ROWS / 128, 1);
        gemm_kernel<false, 1><<<grd, blk>>>(h2, W1, mid, b1, nullptr,
            ROWS, 4 * Dn, Dn, Dn, 4 * Dn, 4 * Dn, 1.0f,
            0LL, 1, 0LL, 1,   0LL, 1, 0LL, 1,   0LL, 1, 0LL, 1);
    }

    // FFN2: out = x2 + mid @ W2 + b2
    {
        dim3 grd(Dn / 64, ROWS / 128, 1);
        gemm_kernel<false, 2><<<grd, blk>>>(mid, W2, out, b2, x2,
            ROWS, Dn, 4 * Dn, 4 * Dn, Dn, Dn, 1.0f,
            0LL, 1, 0LL, 1,   0LL, 1, 0LL, 1,   0LL, 1, 0LL, 1);
    }
}

// round 3
// speedup vs baseline: 1.8486x; 1.8486x over previous
#include <cuda_runtime.h>
#include <cuda_bf16.h>

// Problem constants
#define Tn   2048
#define Dn   1024
#define Hn   16
#define HDn  64
#define Bn   2
#define ROWS (Bn * Tn)   // 4096
#define ZHD  (Bn * Hn)   // 32

// ---------------- scratch (static device globals; no allocations) ----------
__device__ float g_h1 [ROWS * Dn];
__device__ float g_qkv[Bn * Hn * Tn * 192];                // fused q|k|v per (b,h)
__device__ __nv_bfloat16 g_khi [ZHD * Tn * HDn], g_klo [ZHD * Tn * HDn];
__device__ __nv_bfloat16 g_vthi[ZHD * Tn * HDn], g_vtlo[ZHD * Tn * HDn];
__device__ float g_sc [(size_t)ZHD * Tn * Tn];             // 536 MB scores
__device__ float g_att[ROWS * Dn];
__device__ float g_x2 [ROWS * Dn];
__device__ float g_h2 [ROWS * Dn];
__device__ float g_mid[ROWS * 4 * Dn];
__device__ __nv_bfloat16 g_wqkvhi[Hn * 192 * Dn], g_wqkvlo[Hn * 192 * Dn];
__device__ __nv_bfloat16 g_wohi[Dn * Dn],       g_wolo[Dn * Dn];
__device__ __nv_bfloat16 g_w1hi[Dn * 4 * Dn],   g_w1lo[Dn * 4 * Dn];
__device__ __nv_bfloat16 g_w2hi[4 * Dn * Dn],   g_w2lo[4 * Dn * Dn];

// ---------------------------------------------------------------------------
// helpers: split a float into bf16 hi + bf16 lo
// ---------------------------------------------------------------------------
__device__ __forceinline__ void split1(float v, __nv_bfloat16& h, __nv_bfloat16& l) {
    h = __float2bfloat16(v);
    l = __float2bfloat16(v - __bfloat162float(h));
}

__device__ __forceinline__ void cvt_pair(float a, float b, unsigned& hi, unsigned& lo) {
    __nv_bfloat16 ha, la, hb, lb;
    split1(a, ha, la);
    split1(b, hb, lb);
    hi = ((unsigned)__bfloat16_as_ushort(hb) << 16) | (unsigned)__bfloat16_as_ushort(ha);
    lo = ((unsigned)__bfloat16_as_ushort(lb) << 16) | (unsigned)__bfloat16_as_ushort(la);
}

#define MMA_BF16(d, a, b) \
    asm volatile("mma.sync.aligned.m16n8k16.row.col.f32.bf16.bf16.f32 " \
                 "{%0,%1,%2,%3},{%4,%5,%6,%7},{%8,%9},{%0,%1,%2,%3};\n" \
                 : "+f"(d[0]), "+f"(d[1]), "+f"(d[2]), "+f"(d[3]) \
                 : "r"(a[0]), "r"(a[1]), "r"(a[2]), "r"(a[3]), "r"(b[0]), "r"(b[1]))

// ---------------------------------------------------------------------------
// split+transpose: in [z][R][C] fp32 (row stride ldin) -> out [z][C][R] bf16 hi/lo
// block 32x8, tile 32x32
// ---------------------------------------------------------------------------
__global__ void split_transpose(const float* __restrict__ in,
                                __nv_bfloat16* __restrict__ ohi,
                                __nv_bfloat16* __restrict__ olo,
                                int ldin, long long sIn, int ldout, long long sOut)
{
    __shared__ float t[32][33];
    int z = blockIdx.z;
    in  += (long long)z * sIn;
    ohi += (long long)z * sOut;
    olo += (long long)z * sOut;
    int c0 = blockIdx.x * 32, r0 = blockIdx.y * 32;
    int tx = threadIdx.x, ty = threadIdx.y;
#pragma unroll
    for (int i = 0; i < 32; i += 8)
        t[ty + i][tx] = in[(long long)(r0 + ty + i) * ldin + c0 + tx];
    __syncthreads();
#pragma unroll
    for (int i = 0; i < 32; i += 8) {
        float v = t[tx][ty + i];
        __nv_bfloat16 h, l;
        split1(v, h, l);
        long long o = (long long)(c0 + ty + i) * ldout + r0 + tx;
        ohi[o] = h;
        olo[o] = l;
    }
}

// split copy (no transpose): in rows x C fp32 (row stride ldin) -> bf16 hi/lo [rows][C]
__global__ void split_copy(const float* __restrict__ in,
                           __nv_bfloat16* __restrict__ ohi,
                           __nv_bfloat16* __restrict__ olo,
                           long long rows, int C, int ldin)
{
    long long i = (long long)blockIdx.x * blockDim.x + threadIdx.x;
    long long total = rows * (C / 4);
    if (i >= total) return;
    long long r = i / (C / 4);
    int c = (int)(i % (C / 4)) * 4;
    float4 v = *reinterpret_cast<const float4*>(&in[r * ldin + c]);
    unsigned h0, l0, h1, l1;
    cvt_pair(v.x, v.y, h0, l0);
    cvt_pair(v.z, v.w, h1, l1);
    long long o = r * C + c;
    *reinterpret_cast<unsigned*>(&ohi[o])     = h0;
    *reinterpret_cast<unsigned*>(&ohi[o + 2]) = h1;
    *reinterpret_cast<unsigned*>(&olo[o])     = l0;
    *reinterpret_cast<unsigned*>(&olo[o + 2]) = l1;
}

// ---------------------------------------------------------------------------
// bf16x3 tensor-core GEMM: C = alpha * A @ B^T(+epi)
//   A fp32 [M,K] (lda); B pre-split bf16 hi/lo [N,K] (ldb); C fp32 (ldc)
//   EPI: 0 none, 1 bias+relu, 2 bias+residual
//   CAUSAL: skip blocks fully above diagonal (QK^T)
//   KCLAMP: limit K-loop to m0+BM (PV with zeroed upper attn)
// Block: 256 threads, BM=128, BN=64, BK=16. Warps 4(m) x 2(n), warp tile 32x32.
// ---------------------------------------------------------------------------
template <int EPI, bool CAUSAL, bool KCLAMP>
__launch_bounds__(256)
__global__ void gemm_bf16x3(const float* __restrict__ A,
                            const __nv_bfloat16* __restrict__ Bhi,
                            const __nv_bfloat16* __restrict__ Blo,
                            float* __restrict__ C,
                            const float* __restrict__ bias,
                            const float* __restrict__ res,
                            int M, int N, int K,
                            int lda, int ldb, int ldc, float alpha,
                            long long sA1, int dA, long long sA2, int mA,
                            long long sB1, int dB, long long sB2, int mB,
                            long long sC1, int dC, long long sC2, int mC)
{
    constexpr int STW = 12;                 // padded row stride in 32-bit words (8 data + 4 pad)
    __shared__ unsigned sAhi[128 * STW], sAlo[128 * STW];
    __shared__ unsigned sBhi[64 * STW],  sBlo[64 * STW];

    const int m0 = blockIdx.y * 128;
    const int n0 = blockIdx.x * 64;
    if (CAUSAL && n0 >= m0 + 128) return;

    const int z = blockIdx.z;
    A   += (long long)(z / dA) * sA1 + (long long)(z % mA) * sA2;
    Bhi += (long long)(z / dB) * sB1 + (long long)(z % mB) * sB2;
    Blo += (long long)(z / dB) * sB1 + (long long)(z % mB) * sB2;
    const long long coff = (long long)(z / dC) * sC1 + (long long)(z % mC) * sC2;
    C += coff;
    if (EPI == 2) res += coff;

    const int tid  = threadIdx.x;
    const int lane = tid & 31;
    const int w    = tid >> 5;
    const int wm   = (w & 3) * 32;
    const int wn   = (w >> 2) * 32;

    int kend = K;
    if (KCLAMP) kend = min(K, m0 + 128);
    const int nk = kend / 16;

    // loader mapping
    const int la_m = tid >> 2;            // 0..63 (rows la_m and la_m+64)
    const int la_k = (tid & 3) * 4;       // float4 k-offset
    const int lb_n = tid >> 2;            // B row
    const int lb_w = (tid & 3) * 2;       // word offset (elements = lb_w*2)

    float acc[2][4][4];
#pragma unroll
    for (int mt = 0; mt < 2; mt++)
#pragma unroll
        for (int nt = 0; nt < 4; nt++)
#pragma unroll
            for (int j = 0; j < 4; j++) acc[mt][nt][j] = 0.f;

    // ---- prologue: tile 0 -> smem
    {
        float4 a0 = *reinterpret_cast<const float4*>(&A[(long long)(m0 + la_m) * lda + la_k]);
        float4 a1 = *reinterpret_cast<const float4*>(&A[(long long)(m0 + 64 + la_m) * lda + la_k]);
        uint2 bh = *reinterpret_cast<const uint2*>(Bhi + (long long)(n0 + lb_n) * ldb + lb_w * 2);
        uint2 bl = *reinterpret_cast<const uint2*>(Blo + (long long)(n0 + lb_n) * ldb + lb_w * 2);
        unsigned h0, l0, h1, l1;
        cvt_pair(a0.x, a0.y, h0, l0); cvt_pair(a0.z, a0.w, h1, l1);
        sAhi[la_m * STW + (la_k >> 1)] = h0;  sAhi[la_m * STW + (la_k >> 1) + 1] = h1;
        sAlo[la_m * STW + (la_k >> 1)] = l0;  sAlo[la_m * STW + (la_k >> 1) + 1] = l1;
        cvt_pair(a1.x, a1.y, h0, l0); cvt_pair(a1.z, a1.w, h1, l1);
        sAhi[(la_m + 64) * STW + (la_k >> 1)] = h0;  sAhi[(la_m + 64) * STW + (la_k >> 1) + 1] = h1;
        sAlo[(la_m + 64) * STW + (la_k >> 1)] = l0;  sAlo[(la_m + 64) * STW + (la_k >> 1) + 1] = l1;
        sBhi[lb_n * STW + lb_w] = bh.x;  sBhi[lb_n * STW + lb_w + 1] = bh.y;
        sBlo[lb_n * STW + lb_w] = bl.x;  sBlo[lb_n * STW + lb_w + 1] = bl.y;
    }
    __syncthreads();

    float4 pa0, pa1;
    uint2 pbh, pbl;

    for (int kt = 0; kt < nk; kt++) {
        const int knext = (kt + 1) * 16;
        if (kt + 1 < nk) {
            pa0 = *reinterpret_cast<const float4*>(&A[(long long)(m0 + la_m) * lda + knext + la_k]);
            pa1 = *reinterpret_cast<const float4*>(&A[(long long)(m0 + 64 + la_m) * lda + knext + la_k]);
            pbh = *reinterpret_cast<const uint2*>(Bhi + (long long)(n0 + lb_n) * ldb + knext + lb_w * 2);
            pbl = *reinterpret_cast<const uint2*>(Blo + (long long)(n0 + lb_n) * ldb + knext + lb_w * 2);
        }

        // ---- fragments + mma
        {
            const int mr = wm + (lane >> 2);
            const int kb = lane & 3;
            unsigned ah[2][4], al[2][4], bh[4][2], bl[4][2];
#pragma unroll
            for (int mt = 0; mt < 2; mt++) {
                const int r = mr + mt * 16;
                ah[mt][0] = sAhi[r * STW + kb];
                ah[mt][1] = sAhi[(r + 8) * STW + kb];
                ah[mt][2] = sAhi[r * STW + kb + 4];
                ah[mt][3] = sAhi[(r + 8) * STW + kb + 4];
                al[mt][0] = sAlo[r * STW + kb];
                al[mt][1] = sAlo[(r + 8) * STW + kb];
                al[mt][2] = sAlo[r * STW + kb + 4];
                al[mt][3] = sAlo[(r + 8) * STW + kb + 4];
            }
            const int nc = wn + (lane >> 2);
#pragma unroll
            for (int nt = 0; nt < 4; nt++) {
                const int rn = nc + nt * 8;
                bh[nt][0] = sBhi[rn * STW + kb];
                bh[nt][1] = sBhi[rn * STW + kb + 4];
                bl[nt][0] = sBlo[rn * STW + kb];
                bl[nt][1] = sBlo[rn * STW + kb + 4];
            }
#pragma unroll
            for (int mt = 0; mt < 2; mt++)
#pragma unroll
                for (int nt = 0; nt < 4; nt++) {
                    MMA_BF16(acc[mt][nt], ah[mt], bh[nt]);
                    MMA_BF16(acc[mt][nt], ah[mt], bl[nt]);
                    MMA_BF16(acc[mt][nt], al[mt], bh[nt]);
                }
        }
        __syncthreads();
        if (kt + 1 < nk) {
            unsigned h0, l0, h1, l1;
            cvt_pair(pa0.x, pa0.y, h0, l0); cvt_pair(pa0.z, pa0.w, h1, l1);
            sAhi[la_m * STW + (la_k >> 1)] = h0;  sAhi[la_m * STW + (la_k >> 1) + 1] = h1;
            sAlo[la_m * STW + (la_k >> 1)] = l0;  sAlo[la_m * STW + (la_k >> 1) + 1] = l1;
            cvt_pair(pa1.x, pa1.y, h0, l0); cvt_pair(pa1.z, pa1.w, h1, l1);
            sAhi[(la_m + 64) * STW + (la_k >> 1)] = h0;  sAhi[(la_m + 64) * STW + (la_k >> 1) + 1] = h1;
            sAlo[(la_m + 64) * STW + (la_k >> 1)] = l0;  sAlo[(la_m + 64) * STW + (la_k >> 1) + 1] = l1;
            sBhi[lb_n * STW + lb_w] = pbh.x;  sBhi[lb_n * STW + lb_w + 1] = pbh.y;
            sBlo[lb_n * STW + lb_w] = pbl.x;  sBlo[lb_n * STW + lb_w + 1] = pbl.y;
        }
        __syncthreads();
    }

    // ---- epilogue
#pragma unroll
    for (int mt = 0; mt < 2; mt++)
#pragma unroll
        for (int nt = 0; nt < 4; nt++) {
            const float* a4 = acc[mt][nt];
            const long long r0 = m0 + wm + mt * 16 + (lane >> 2);
            const long long r1 = r0 + 8;
            const int cc = n0 + wn + nt * 8 + (lane & 3) * 2;
            float2 u0 = make_float2(a4[0] * alpha, a4[1] * alpha);
            float2 u1 = make_float2(a4[2] * alpha, a4[3] * alpha);
            if (EPI >= 1) {
                float2 bv = *reinterpret_cast<const float2*>(&bias[cc]);
                u0.x += bv.x; u0.y += bv.y; u1.x += bv.x; u1.y += bv.y;
            }
            if (EPI == 1) {
                u0.x = fmaxf(u0.x, 0.f); u0.y = fmaxf(u0.y, 0.f);
                u1.x = fmaxf(u1.x, 0.f); u1.y = fmaxf(u1.y, 0.f);
            }
            if (EPI == 2) {
                float2 q0 = *reinterpret_cast<const float2*>(&res[r0 * ldc + cc]);
                float2 q1 = *reinterpret_cast<const float2*>(&res[r1 * ldc + cc]);
                u0.x += q0.x; u0.y += q0.y; u1.x += q1.x; u1.y += q1.y;
            }
            *reinterpret_cast<float2*>(&C[r0 * ldc + cc]) = u0;
            *reinterpret_cast<float2*>(&C[r1 * ldc + cc]) = u1;
        }
}

// ---------------------------------------------------------------------------
// LayerNorm over last dim (1024). One block (256 threads) per row.
// ---------------------------------------------------------------------------
__launch_bounds__(256)
__global__ void ln_kernel(const float* __restrict__ x,
                          const float* __restrict__ g,
                          const float* __restrict__ be,
                          float* __restrict__ out)
{
    long long row = blockIdx.x;
    const float* xr = x + row * Dn;
    float* outr = out + row * Dn;
    int tid = threadIdx.x;

    float v[4];
    float s = 0.f;
#pragma unroll
    for (int i = 0; i < 4; i++) { v[i] = xr[tid + 256 * i]; s += v[i]; }

    __shared__ float red[8];
    __shared__ float sh_mu, sh_rstd;

#pragma unroll
    for (int o = 16; o > 0; o >>= 1) s += __shfl_xor_sync(0xffffffffu, s, o);
    if ((tid & 31) == 0) red[tid >> 5] = s;
    __syncthreads();
    if (tid == 0) {
        float t = 0.f;
        for (int i = 0; i < 8; i++) t += red[i];
        sh_mu = t * (1.0f / Dn);
    }
    __syncthreads();
    float mu = sh_mu;

    float ss = 0.f;
#pragma unroll
    for (int i = 0; i < 4; i++) { float d = v[i] - mu; ss += d * d; }
#pragma unroll
    for (int o = 16; o > 0; o >>= 1) ss += __shfl_xor_sync(0xffffffffu, ss, o);
    if ((tid & 31) == 0) red[tid >> 5] = ss;
    __syncthreads();
    if (tid == 0) {
        float t = 0.f;
        for (int i = 0; i < 8; i++) t += red[i];
        sh_rstd = rsqrtf(t * (1.0f / Dn) + 1e-5f);
    }
    __syncthreads();
    float rstd = sh_rstd;

#pragma unroll
    for (int i = 0; i < 4; i++) {
        int c = tid + 256 * i;
        outr[c] = (v[i] - mu) * rstd * g[c] + be[c];
    }
}

// ---------------------------------------------------------------------------
// Causal softmax in place, single pass, register-cached exp. One block per row.
// Beyond-boundary entries written 0.
// ---------------------------------------------------------------------------
__launch_bounds__(256)
__global__ void softmax_kernel(float* __restrict__ S)
{
    long long row = blockIdx.x;
    const int t = (int)(row & (Tn - 1));
    const int n = t + 1;
    float* p = S + row * (long long)Tn;
    const int tid = threadIdx.x;

    float4 va = *reinterpret_cast<const float4*>(&p[tid * 4]);
    float4 vb = *reinterpret_cast<const float4*>(&p[1024 + tid * 4]);
    float vals[8] = {va.x, va.y, va.z, va.w, vb.x, vb.y, vb.z, vb.w};
    int cols[8];
#pragma unroll
    for (int j = 0; j < 8; j++) cols[j] = (j < 4) ? tid * 4 + j : 1024 + tid * 4 + (j - 4);

    __shared__ float red[8];
    __shared__ float sh;

    float mx = -3.4e38f;
#pragma unroll
    for (int j = 0; j < 8; j++) if (cols[j] < n) mx = fmaxf(mx, vals[j]);
#pragma unroll
    for (int o = 16; o > 0; o >>= 1) mx = fmaxf(mx, __shfl_xor_sync(0xffffffffu, mx, o));
    if ((tid & 31) == 0) red[tid >> 5] = mx;
    __syncthreads();
    if (tid == 0) {
        float m2 = red[0];
        for (int i = 1; i < 8; i++) m2 = fmaxf(m2, red[i]);
        sh = m2;
    }
    __syncthreads();
    mx = sh;

    float e[8];
    float s = 0.f;
#pragma unroll
    for (int j = 0; j < 8; j++) {
        e[j] = (cols[j] < n) ? __expf(vals[j] - mx) : 0.f;
        s += e[j];
    }
#pragma unroll
    for (int o = 16; o > 0; o >>= 1) s += __shfl_xor_sync(0xffffffffu, s, o);
    if ((tid & 31) == 0) red[tid >> 5] = s;
    __syncthreads();
    if (tid == 0) {
        float t2 = 0.f;
        for (int i = 0; i < 8; i++) t2 += red[i];
        sh = 1.0f / t2;
    }
    __syncthreads();
    const float inv = sh;

    float4 o0 = make_float4(e[0] * inv, e[1] * inv, e[2] * inv, e[3] * inv);
    float4 o1 = make_float4(e[4] * inv, e[5] * inv, e[6] * inv, e[7] * inv);
    *reinterpret_cast<float4*>(&p[tid * 4]) = o0;
    *reinterpret_cast<float4*>(&p[1024 + tid * 4]) = o1;
}

// ---------------------------------------------------------------------------
extern "C" void kernel_launch(void* const* d_in, const int* in_sizes, int n_in,
                              void* d_out, int out_size)
{
    const float* x   = (const float*)d_in[0];
    const float* Wq  = (const float*)d_in[1];
    const float* Wk  = (const float*)d_in[2];
    const float* Wv  = (const float*)d_in[3];
    const float* Wo  = (const float*)d_in[4];
    const float* bo  = (const float*)d_in[5];
    const float* W1  = (const float*)d_in[6];
    const float* b1  = (const float*)d_in[7];
    const float* W2  = (const float*)d_in[8];
    const float* b2  = (const float*)d_in[9];
    const float* g1  = (const float*)d_in[10];
    const float* be1 = (const float*)d_in[11];
    const float* g2  = (const float*)d_in[12];
    const float* be2 = (const float*)d_in[13];
    float* out = (float*)d_out;

    float *h1, *qkv, *sc, *att, *x2, *h2, *mid;
    __nv_bfloat16 *khi, *klo, *vthi, *vtlo;
    __nv_bfloat16 *wqkvhi, *wqkvlo, *wohi, *wolo, *w1hi, *w1lo, *w2hi, *w2lo;
    cudaGetSymbolAddress((void**)&h1,   g_h1);
    cudaGetSymbolAddress((void**)&qkv,  g_qkv);
    cudaGetSymbolAddress((void**)&khi,  g_khi);
    cudaGetSymbolAddress((void**)&klo,  g_klo);
    cudaGetSymbolAddress((void**)&vthi, g_vthi);
    cudaGetSymbolAddress((void**)&vtlo, g_vtlo);
    cudaGetSymbolAddress((void**)&sc,   g_sc);
    cudaGetSymbolAddress((void**)&att,  g_att);
    cudaGetSymbolAddress((void**)&x2,   g_x2);
    cudaGetSymbolAddress((void**)&h2,   g_h2);
    cudaGetSymbolAddress((void**)&mid,  g_mid);
    cudaGetSymbolAddress((void**)&wqkvhi, g_wqkvhi);
    cudaGetSymbolAddress((void**)&wqkvlo, g_wqkvlo);
    cudaGetSymbolAddress((void**)&wohi, g_wohi);
    cudaGetSymbolAddress((void**)&wolo, g_wolo);
    cudaGetSymbolAddress((void**)&w1hi, g_w1hi);
    cudaGetSymbolAddress((void**)&w1lo, g_w1lo);
    cudaGetSymbolAddress((void**)&w2hi, g_w2hi);
    cudaGetSymbolAddress((void**)&w2lo, g_w2lo);

    dim3 blk(256);
    dim3 tblk(32, 8);

    // ---- weight pre-split/transpose (per launch; ~30us of bandwidth)
    // Wq/Wk/Wv [H,D,HD] -> wqkvT [H, 192, D] (q cols 0-63, k 64-127, v 128-191)
    split_transpose<<<dim3(HDn / 32, Dn / 32, Hn), tblk>>>(
        Wq, wqkvhi + 0 * Dn * HDn, wqkvlo + 0 * Dn * HDn,
        HDn, (long long)Dn * HDn, Dn, (long long)192 * Dn);
    split_transpose<<<dim3(HDn / 32, Dn / 32, Hn), tblk>>>(
        Wk, wqkvhi + 1 * Dn * HDn, wqkvlo + 1 * Dn * HDn,
        HDn, (long long)Dn * HDn, Dn, (long long)192 * Dn);
    split_transpose<<<dim3(HDn / 32, Dn / 32, Hn), tblk>>>(
        Wv, wqkvhi + 2 * Dn * HDn, wqkvlo + 2 * Dn * HDn,
        HDn, (long long)Dn * HDn, Dn, (long long)192 * Dn);
    // Wo [D,D] -> [D,D]^T
    split_transpose<<<dim3(Dn / 32, Dn / 32, 1), tblk>>>(
        Wo, wohi, wolo, Dn, 0LL, Dn, 0LL);
    // W1 [D,4D] -> [4D,D]
    split_transpose<<<dim3(4 * Dn / 32, Dn / 32, 1), tblk>>>(
        W1, w1hi, w1lo, 4 * Dn, 0LL, Dn, 0LL);
    // W2 [4D,D] -> [D,4D]
    split_transpose<<<dim3(Dn / 32, 4 * Dn / 32, 1), tblk>>>(
        W2, w2hi, w2lo, Dn, 0LL, 4 * Dn, 0LL);

    // ---- LN1: x -> h1
    ln_kernel<<<ROWS, blk>>>(x, g1, be1, h1);

    // ---- fused QKV: qkv[z][T][192] = h1(b) @ wqkvT(h)^T ; z = b*H + h
    {
        dim3 grd(192 / 64, Tn / 128, ZHD);
        gemm_bf16x3<0, false, false><<<grd, blk>>>(
            h1, wqkvhi, wqkvlo, qkv, nullptr, nullptr,
            Tn, 192, Dn, Dn, Dn, 192, 1.0f,
            (long long)Tn * Dn, Hn, 0LL, 1,                  // A: per batch b = z/H
            0LL, 1, (long long)192 * Dn, Hn,                 // B: per head h = z%H
            (long long)Tn * 192, 1, 0LL, 1);                 // C: per z
    }

    // ---- K split (rows of qkv at offset 64), V transpose-split (offset 128)
    {
        long long krows = (long long)ZHD * Tn;
        int total = (int)(krows * (HDn / 4));
        split_copy<<<(total + 255) / 256, blk>>>(qkv + 64, khi, klo, krows, HDn, 192);
        split_transpose<<<dim3(HDn / 32, Tn / 32, ZHD), tblk>>>(
            qkv + 128, vthi, vtlo, 192, (long long)Tn * 192, Tn, (long long)HDn * Tn);
    }

    // ---- scores = (Q @ K^T) * D^-0.5, causal-skipped
    {
        dim3 grd(Tn / 64, Tn / 128, ZHD);
        gemm_bf16x3<0, true, false><<<grd, blk>>>(
            qkv, khi, klo, sc, nullptr, nullptr,
            Tn, Tn, HDn, 192, HDn, Tn, 0.03125f,
            (long long)Tn * 192, 1, 0LL, 1,
            (long long)Tn * HDn, 1, 0LL, 1,
            (long long)Tn * Tn, 1, 0LL, 1);
    }

    // ---- causal softmax (in place; zero-fills masked region)
    softmax_kernel<<<ZHD * Tn, blk>>>(sc);

    // ---- attn @ V -> att (concat layout), K-loop clamped to causal extent
    {
        dim3 grd(HDn / 64, Tn / 128, ZHD);
        gemm_bf16x3<0, false, true><<<grd, blk>>>(
            sc, vthi, vtlo, att, nullptr, nullptr,
            Tn, HDn, Tn, Tn, Tn, Dn, 1.0f,
            (long long)Tn * Tn, 1, 0LL, 1,
            (long long)HDn * Tn, 1, 0LL, 1,
            (long long)Tn * Dn, Hn, (long long)HDn, Hn);     // C: + b*T*D + h*HD
    }

    // ---- O projection + bias + residual: x2 = x + att @ Wo + bo
    {
        dim3 grd(Dn / 64, ROWS / 128, 1);
        gemm_bf16x3<2, false, false><<<grd, blk>>>(
            att, wohi, wolo, x2, bo, x,
            ROWS, Dn, Dn, Dn, Dn, Dn, 1.0f,
            0LL, 1, 0LL, 1, 0LL, 1, 0LL, 1, 0LL, 1, 0LL, 1);
    }

    // ---- LN2
    ln_kernel<<<ROWS, blk>>>(x2, g2, be2, h2);

    // ---- FFN1: mid = relu(h2 @ W1 + b1)
    {
        dim3 grd(4 * Dn / 64, ROWS / 128, 1);
        gemm_bf16x3<1, false, false><<<grd, blk>>>(
            h2, w1hi, w1lo, mid, b1, nullptr,
            ROWS, 4 * Dn, Dn, Dn, Dn, 4 * Dn, 1.0f,
            0LL, 1, 0LL, 1, 0LL, 1, 0LL, 1, 0LL, 1, 0LL, 1);
    }

    // ---- FFN2: out = x2 + mid @ W2 + b2
    {
        dim3 grd(Dn / 64, ROWS / 128, 1);
        gemm_bf16x3<2, false, false><<<grd, blk>>>(
            mid, w2hi, w2lo, out, b2, x2,
            ROWS, Dn, 4 * Dn, 4 * Dn, 4 * Dn, Dn, 1.0f,
            0LL, 1, 0LL, 1, 0LL, 1, 0LL, 1, 0LL, 1, 0LL, 1);
    }
}

// round 4
// speedup vs baseline: 2.1486x; 1.1622x over previous
#include <cuda_runtime.h>
#include <cuda_bf16.h>

// Problem constants
#define Tn   2048
#define Dn   1024
#define Hn   16
#define HDn  64
#define Bn   2
#define ROWS (Bn * Tn)   // 4096
#define ZHD  (Bn * Hn)   // 32

// ---------------- scratch (static device globals; no allocations) ----------
__device__ float g_h1 [ROWS * Dn];
__device__ float g_qkv[Bn * Hn * Tn * 192];                // fused q|k|v per (b,h)
__device__ __nv_bfloat16 g_khi [ZHD * Tn * HDn], g_klo [ZHD * Tn * HDn];
__device__ __nv_bfloat16 g_vthi[ZHD * Tn * HDn], g_vtlo[ZHD * Tn * HDn];
__device__ float g_att[ROWS * Dn];
__device__ float g_x2 [ROWS * Dn];
__device__ float g_h2 [ROWS * Dn];
__device__ float g_mid[ROWS * 4 * Dn];
__device__ __nv_bfloat16 g_wqkvhi[Hn * 192 * Dn], g_wqkvlo[Hn * 192 * Dn];
__device__ __nv_bfloat16 g_wohi[Dn * Dn],       g_wolo[Dn * Dn];
__device__ __nv_bfloat16 g_w1hi[Dn * 4 * Dn],   g_w1lo[Dn * 4 * Dn];
__device__ __nv_bfloat16 g_w2hi[4 * Dn * Dn],   g_w2lo[4 * Dn * Dn];

// ---------------------------------------------------------------------------
__device__ __forceinline__ void split1(float v, __nv_bfloat16& h, __nv_bfloat16& l) {
    h = __float2bfloat16(v);
    l = __float2bfloat16(v - __bfloat162float(h));
}

__device__ __forceinline__ void cvt_pair(float a, float b, unsigned& hi, unsigned& lo) {
    __nv_bfloat16 ha, la, hb, lb;
    split1(a, ha, la);
    split1(b, hb, lb);
    hi = ((unsigned)__bfloat16_as_ushort(hb) << 16) | (unsigned)__bfloat16_as_ushort(ha);
    lo = ((unsigned)__bfloat16_as_ushort(lb) << 16) | (unsigned)__bfloat16_as_ushort(la);
}

#define MMA_BF16(d, a, b) \
    asm volatile("mma.sync.aligned.m16n8k16.row.col.f32.bf16.bf16.f32 " \
                 "{%0,%1,%2,%3},{%4,%5,%6,%7},{%8,%9},{%0,%1,%2,%3};\n" \
                 : "+f"(d[0]), "+f"(d[1]), "+f"(d[2]), "+f"(d[3]) \
                 : "r"(a[0]), "r"(a[1]), "r"(a[2]), "r"(a[3]), "r"(b[0]), "r"(b[1]))

__device__ __forceinline__ unsigned smem_u32(const void* p) {
    return (unsigned)__cvta_generic_to_shared(p);
}
__device__ __forceinline__ void cp16(unsigned dst, const void* src) {
    asm volatile("cp.async.cg.shared.global [%0],[%1],16;\n" :: "r"(dst), "l"(src));
}

// ---------------------------------------------------------------------------
// split+transpose: in [z][R][C] fp32 (row stride ldin) -> out [z][C][R] bf16 hi/lo
// ---------------------------------------------------------------------------
__global__ void split_transpose(const float* __restrict__ in,
                                __nv_bfloat16* __restrict__ ohi,
                                __nv_bfloat16* __restrict__ olo,
                                int ldin, long long sIn, int ldout, long long sOut)
{
    __shared__ float t[32][33];
    int z = blockIdx.z;
    in  += (long long)z * sIn;
    ohi += (long long)z * sOut;
    olo += (long long)z * sOut;
    int c0 = blockIdx.x * 32, r0 = blockIdx.y * 32;
    int tx = threadIdx.x, ty = threadIdx.y;
#pragma unroll
    for (int i = 0; i < 32; i += 8)
        t[ty + i][tx] = in[(long long)(r0 + ty + i) * ldin + c0 + tx];
    __syncthreads();
#pragma unroll
    for (int i = 0; i < 32; i += 8) {
        float v = t[tx][ty + i];
        __nv_bfloat16 h, l;
        split1(v, h, l);
        long long o = (long long)(c0 + ty + i) * ldout + r0 + tx;
        ohi[o] = h;
        olo[o] = l;
    }
}

// split copy (no transpose)
__global__ void split_copy(const float* __restrict__ in,
                           __nv_bfloat16* __restrict__ ohi,
                           __nv_bfloat16* __restrict__ olo,
                           long long rows, int C, int ldin)
{
    long long i = (long long)blockIdx.x * blockDim.x + threadIdx.x;
    long long total = rows * (C / 4);
    if (i >= total) return;
    long long r = i / (C / 4);
    int c = (int)(i % (C / 4)) * 4;
    float4 v = *reinterpret_cast<const float4*>(&in[r * ldin + c]);
    unsigned h0, l0, h1, l1;
    cvt_pair(v.x, v.y, h0, l0);
    cvt_pair(v.z, v.w, h1, l1);
    long long o = r * C + c;
    *reinterpret_cast<unsigned*>(&ohi[o])     = h0;
    *reinterpret_cast<unsigned*>(&ohi[o + 2]) = h1;
    *reinterpret_cast<unsigned*>(&olo[o])     = l0;
    *reinterpret_cast<unsigned*>(&olo[o + 2]) = l1;
}

// ---------------------------------------------------------------------------
// bf16x3 tensor-core GEMM (dense path): C = alpha * A @ B^T (+epi)
// ---------------------------------------------------------------------------
template <int EPI>
__launch_bounds__(256)
__global__ void gemm_bf16x3(const float* __restrict__ A,
                            const __nv_bfloat16* __restrict__ Bhi,
                            const __nv_bfloat16* __restrict__ Blo,
                            float* __restrict__ C,
                            const float* __restrict__ bias,
                            const float* __restrict__ res,
                            int M, int N, int K,
                            int lda, int ldb, int ldc, float alpha,
                            long long sA1, int dA, long long sA2, int mA,
                            long long sB1, int dB, long long sB2, int mB,
                            long long sC1, int dC, long long sC2, int mC)
{
    constexpr int STW = 12;
    __shared__ unsigned sAhi[128 * STW], sAlo[128 * STW];
    __shared__ unsigned sBhi[64 * STW],  sBlo[64 * STW];

    const int m0 = blockIdx.y * 128;
    const int n0 = blockIdx.x * 64;

    const int z = blockIdx.z;
    A   += (long long)(z / dA) * sA1 + (long long)(z % mA) * sA2;
    Bhi += (long long)(z / dB) * sB1 + (long long)(z % mB) * sB2;
    Blo += (long long)(z / dB) * sB1 + (long long)(z % mB) * sB2;
    const long long coff = (long long)(z / dC) * sC1 + (long long)(z % mC) * sC2;
    C += coff;
    if (EPI == 2) res += coff;

    const int tid  = threadIdx.x;
    const int lane = tid & 31;
    const int w    = tid >> 5;
    const int wm   = (w & 3) * 32;
    const int wn   = (w >> 2) * 32;

    const int nk = K / 16;

    const int la_m = tid >> 2;
    const int la_k = (tid & 3) * 4;
    const int lb_n = tid >> 2;
    const int lb_w = (tid & 3) * 2;

    float acc[2][4][4];
#pragma unroll
    for (int mt = 0; mt < 2; mt++)
#pragma unroll
        for (int nt = 0; nt < 4; nt++)
#pragma unroll
            for (int j = 0; j < 4; j++) acc[mt][nt][j] = 0.f;

    {
        float4 a0 = *reinterpret_cast<const float4*>(&A[(long long)(m0 + la_m) * lda + la_k]);
        float4 a1 = *reinterpret_cast<const float4*>(&A[(long long)(m0 + 64 + la_m) * lda + la_k]);
        uint2 bh = *reinterpret_cast<const uint2*>(Bhi + (long long)(n0 + lb_n) * ldb + lb_w * 2);
        uint2 bl = *reinterpret_cast<const uint2*>(Blo + (long long)(n0 + lb_n) * ldb + lb_w * 2);
        unsigned h0, l0, h1, l1;
        cvt_pair(a0.x, a0.y, h0, l0); cvt_pair(a0.z, a0.w, h1, l1);
        sAhi[la_m * STW + (la_k >> 1)] = h0;  sAhi[la_m * STW + (la_k >> 1) + 1] = h1;
        sAlo[la_m * STW + (la_k >> 1)] = l0;  sAlo[la_m * STW + (la_k >> 1) + 1] = l1;
        cvt_pair(a1.x, a1.y, h0, l0); cvt_pair(a1.z, a1.w, h1, l1);
        sAhi[(la_m + 64) * STW + (la_k >> 1)] = h0;  sAhi[(la_m + 64) * STW + (la_k >> 1) + 1] = h1;
        sAlo[(la_m + 64) * STW + (la_k >> 1)] = l0;  sAlo[(la_m + 64) * STW + (la_k >> 1) + 1] = l1;
        sBhi[lb_n * STW + lb_w] = bh.x;  sBhi[lb_n * STW + lb_w + 1] = bh.y;
        sBlo[lb_n * STW + lb_w] = bl.x;  sBlo[lb_n * STW + lb_w + 1] = bl.y;
    }
    __syncthreads();

    float4 pa0, pa1;
    uint2 pbh, pbl;

    for (int kt = 0; kt < nk; kt++) {
        const int knext = (kt + 1) * 16;
        if (kt + 1 < nk) {
            pa0 = *reinterpret_cast<const float4*>(&A[(long long)(m0 + la_m) * lda + knext + la_k]);
            pa1 = *reinterpret_cast<const float4*>(&A[(long long)(m0 + 64 + la_m) * lda + knext + la_k]);
            pbh = *reinterpret_cast<const uint2*>(Bhi + (long long)(n0 + lb_n) * ldb + knext + lb_w * 2);
            pbl = *reinterpret_cast<const uint2*>(Blo + (long long)(n0 + lb_n) * ldb + knext + lb_w * 2);
        }

        {
            const int mr = wm + (lane >> 2);
            const int kb = lane & 3;
            unsigned ah[2][4], al[2][4], bh[4][2], bl[4][2];
#pragma unroll
            for (int mt = 0; mt < 2; mt++) {
                const int r = mr + mt * 16;
                ah[mt][0] = sAhi[r * STW + kb];
                ah[mt][1] = sAhi[(r + 8) * STW + kb];
                ah[mt][2] = sAhi[r * STW + kb + 4];
                ah[mt][3] = sAhi[(r + 8) * STW + kb + 4];
                al[mt][0] = sAlo[r * STW + kb];
                al[mt][1] = sAlo[(r + 8) * STW + kb];
                al[mt][2] = sAlo[r * STW + kb + 4];
                al[mt][3] = sAlo[(r + 8) * STW + kb + 4];
            }
            const int nc = wn + (lane >> 2);
#pragma unroll
            for (int nt = 0; nt < 4; nt++) {
                const int rn = nc + nt * 8;
                bh[nt][0] = sBhi[rn * STW + kb];
                bh[nt][1] = sBhi[rn * STW + kb + 4];
                bl[nt][0] = sBlo[rn * STW + kb];
                bl[nt][1] = sBlo[rn * STW + kb + 4];
            }
            // pass-major: each accumulator retouched only every 8 MMAs
#pragma unroll
            for (int mt = 0; mt < 2; mt++)
#pragma unroll
                for (int nt = 0; nt < 4; nt++) MMA_BF16(acc[mt][nt], ah[mt], bh[nt]);
#pragma unroll
            for (int mt = 0; mt < 2; mt++)
#pragma unroll
                for (int nt = 0; nt < 4; nt++) MMA_BF16(acc[mt][nt], ah[mt], bl[nt]);
#pragma unroll
            for (int mt = 0; mt < 2; mt++)
#pragma unroll
                for (int nt = 0; nt < 4; nt++) MMA_BF16(acc[mt][nt], al[mt], bh[nt]);
        }
        __syncthreads();
        if (kt + 1 < nk) {
            unsigned h0, l0, h1, l1;
            cvt_pair(pa0.x, pa0.y, h0, l0); cvt_pair(pa0.z, pa0.w, h1, l1);
            sAhi[la_m * STW + (la_k >> 1)] = h0;  sAhi[la_m * STW + (la_k >> 1) + 1] = h1;
            sAlo[la_m * STW + (la_k >> 1)] = l0;  sAlo[la_m * STW + (la_k >> 1) + 1] = l1;
            cvt_pair(pa1.x, pa1.y, h0, l0); cvt_pair(pa1.z, pa1.w, h1, l1);
            sAhi[(la_m + 64) * STW + (la_k >> 1)] = h0;  sAhi[(la_m + 64) * STW + (la_k >> 1) + 1] = h1;
            sAlo[(la_m + 64) * STW + (la_k >> 1)] = l0;  sAlo[(la_m + 64) * STW + (la_k >> 1) + 1] = l1;
            sBhi[lb_n * STW + lb_w] = pbh.x;  sBhi[lb_n * STW + lb_w + 1] = pbh.y;
            sBlo[lb_n * STW + lb_w] = pbl.x;  sBlo[lb_n * STW + lb_w + 1] = pbl.y;
        }
        __syncthreads();
    }

#pragma unroll
    for (int mt = 0; mt < 2; mt++)
#pragma unroll
        for (int nt = 0; nt < 4; nt++) {
            const float* a4 = acc[mt][nt];
            const long long r0 = m0 + wm + mt * 16 + (lane >> 2);
            const long long r1 = r0 + 8;
            const int cc = n0 + wn + nt * 8 + (lane & 3) * 2;
            float2 u0 = make_float2(a4[0] * alpha, a4[1] * alpha);
            float2 u1 = make_float2(a4[2] * alpha, a4[3] * alpha);
            if (EPI >= 1) {
                float2 bv = *reinterpret_cast<const float2*>(&bias[cc]);
                u0.x += bv.x; u0.y += bv.y; u1.x += bv.x; u1.y += bv.y;
            }
            if (EPI == 1) {
                u0.x = fmaxf(u0.x, 0.f); u0.y = fmaxf(u0.y, 0.f);
                u1.x = fmaxf(u1.x, 0.f); u1.y = fmaxf(u1.y, 0.f);
            }
            if (EPI == 2) {
                float2 q0 = *reinterpret_cast<const float2*>(&res[r0 * ldc + cc]);
                float2 q1 = *reinterpret_cast<const float2*>(&res[r1 * ldc + cc]);
                u0.x += q0.x; u0.y += q0.y; u1.x += q1.x; u1.y += q1.y;
            }
            *reinterpret_cast<float2*>(&C[r0 * ldc + cc]) = u0;
            *reinterpret_cast<float2*>(&C[r1 * ldc + cc]) = u1;
        }
}

// ---------------------------------------------------------------------------
// Flash attention: per (b,h), 128 query rows per block, stream K/V in 64-key
// tiles through smem (cp.async). bf16x3 MMAs for both QK^T and PV, online
// softmax with fp32 stats, causal clamp. Writes concat att layout directly.
// grid = (Tn/128, ZHD), block = 256 (8 warps, each owns 16 query rows).
// ---------------------------------------------------------------------------
__launch_bounds__(256)
__global__ void flash_kernel(const float* __restrict__ qkv,
                             const __nv_bfloat16* __restrict__ Khi,
                             const __nv_bfloat16* __restrict__ Klo,
                             const __nv_bfloat16* __restrict__ Vhi,
                             const __nv_bfloat16* __restrict__ Vlo,
                             float* __restrict__ att)
{
    constexpr int KVW = 64 * 36;                 // words per array
    __shared__ __align__(16) unsigned s_kv[4 * KVW];   // 36,864 B (also Q staging)

    const int z  = blockIdx.y;
    const int m0 = blockIdx.x * 128;
    const int tid = threadIdx.x, lane = tid & 31, w = tid >> 5;
    const int qr = lane >> 2;          // 0..7
    const int cb = (lane & 3) * 2;     // column base within n8 tile

    // ---- stage Q (fp32) into smem, build scaled bf16 hi/lo A-fragments
    unsigned qh[4][4], ql[4][4];
    {
        float* sQ = (float*)s_kv;      // 128 x 68 floats = 34,816 B
        const float* Qg = qkv + (long long)z * Tn * 192 + (long long)m0 * 192;
#pragma unroll
        for (int i = 0; i < 8; i++) {
            int idx = tid + 256 * i;   // 0..2047 float4s
            int r = idx >> 4, c4 = idx & 15;
            float4 v = *reinterpret_cast<const float4*>(Qg + (long long)r * 192 + c4 * 4);
            *reinterpret_cast<float4*>(sQ + r * 68 + c4 * 4) = v;
        }
        __syncthreads();
        const int ra = w * 16 + qr;
        const float sc = 0.03125f;     // D^-0.5 folded into Q
#pragma unroll
        for (int c = 0; c < 4; c++) {
            float p0 = sQ[ra * 68 + c * 16 + cb]           * sc;
            float p1 = sQ[ra * 68 + c * 16 + cb + 1]       * sc;
            float p2 = sQ[(ra + 8) * 68 + c * 16 + cb]     * sc;
            float p3 = sQ[(ra + 8) * 68 + c * 16 + cb + 1] * sc;
            float p4 = sQ[ra * 68 + c * 16 + cb + 8]       * sc;
            float p5 = sQ[ra * 68 + c * 16 + cb + 9]       * sc;
            float p6 = sQ[(ra + 8) * 68 + c * 16 + cb + 8] * sc;
            float p7 = sQ[(ra + 8) * 68 + c * 16 + cb + 9] * sc;
            cvt_pair(p0, p1, qh[c][0], ql[c][0]);
            cvt_pair(p2, p3, qh[c][1], ql[c][1]);
            cvt_pair(p4, p5, qh[c][2], ql[c][2]);
            cvt_pair(p6, p7, qh[c][3], ql[c][3]);
        }
        __syncthreads();
    }

    float m0s = -1e30f, m1s = -1e30f;   // running row maxima (rows qr, qr+8)
    float l0 = 0.f, l1 = 0.f;           // running row sums
    float acc_o[8][4];
#pragma unroll
    for (int nt = 0; nt < 8; nt++)
#pragma unroll
        for (int j = 0; j < 4; j++) acc_o[nt][j] = 0.f;

    const int nkb = blockIdx.x * 2 + 2;        // causal: keys < m0+128
    const long long kbaseK = (long long)z * Tn * HDn;
    const long long kbaseV = (long long)z * HDn * Tn;
    const int rga = m0 + w * 16 + qr;          // global query rows
    const int rgb = rga + 8;

    for (int it = 0; it < nkb; it++) {
        // ---- load K/V tile (single buffer, cp.async)
        {
            const __nv_bfloat16* pKh = Khi + kbaseK + (long long)it * 64 * HDn;
            const __nv_bfloat16* pKl = Klo + kbaseK + (long long)it * 64 * HDn;
            const __nv_bfloat16* pVh = Vhi + kbaseV + it * 64;
            const __nv_bfloat16* pVl = Vlo + kbaseV + it * 64;
#pragma unroll
            for (int i = 0; i < 2; i++) {
                int idx = tid + 256 * i;       // 0..511
                int r = idx >> 3, s = idx & 7;
                unsigned doff = r * 36 + s * 4;
                cp16(smem_u32(s_kv + doff),            pKh + r * HDn + s * 8);
                cp16(smem_u32(s_kv + KVW + doff),      pKl + r * HDn + s * 8);
                cp16(smem_u32(s_kv + 2 * KVW + doff),  pVh + (long long)r * Tn + s * 8);
                cp16(smem_u32(s_kv + 3 * KVW + doff),  pVl + (long long)r * Tn + s * 8);
            }
            asm volatile("cp.async.commit_group;");
            asm volatile("cp.async.wait_group 0;");
        }
        __syncthreads();

        // ---- S = Q K^T (bf16x3)
        float s[8][4];
#pragma unroll
        for (int nt = 0; nt < 8; nt++)
#pragma unroll
            for (int j = 0; j < 4; j++) s[nt][j] = 0.f;

        unsigned bh[8][2], bl[8][2];
#pragma unroll
        for (int c = 0; c < 4; c++) {
#pragma unroll
            for (int nt = 0; nt < 8; nt++) {
                int off = (nt * 8 + qr) * 36 + c * 8 + (lane & 3);
                bh[nt][0] = s_kv[off];        bh[nt][1] = s_kv[off + 4];
                bl[nt][0] = s_kv[KVW + off];  bl[nt][1] = s_kv[KVW + off + 4];
            }
#pragma unroll
            for (int nt = 0; nt < 8; nt++) MMA_BF16(s[nt], qh[c], bh[nt]);
#pragma unroll
            for (int nt = 0; nt < 8; nt++) MMA_BF16(s[nt], qh[c], bl[nt]);
#pragma unroll
            for (int nt = 0; nt < 8; nt++) MMA_BF16(s[nt], ql[c], bh[nt]);
        }

        // ---- causal mask
        const int cg0 = it * 64 + cb;
        if (it * 64 + 63 > rga) {
#pragma unroll
            for (int nt = 0; nt < 8; nt++) {
                int cg = cg0 + nt * 8;
                if (cg > rga)     s[nt][0] = -1e30f;
                if (cg + 1 > rga) s[nt][1] = -1e30f;
                if (cg > rgb)     s[nt][2] = -1e30f;
                if (cg + 1 > rgb) s[nt][3] = -1e30f;
            }
        }

        // ---- online softmax update
        float ml0 = -1e30f, ml1 = -1e30f;
#pragma unroll
        for (int nt = 0; nt < 8; nt++) {
            ml0 = fmaxf(ml0, fmaxf(s[nt][0], s[nt][1]));
            ml1 = fmaxf(ml1, fmaxf(s[nt][2], s[nt][3]));
        }
        ml0 = fmaxf(ml0, __shfl_xor_sync(0xffffffffu, ml0, 1));
        ml0 = fmaxf(ml0, __shfl_xor_sync(0xffffffffu, ml0, 2));
        ml1 = fmaxf(ml1, __shfl_xor_sync(0xffffffffu, ml1, 1));
        ml1 = fmaxf(ml1, __shfl_xor_sync(0xffffffffu, ml1, 2));
        float mn0 = fmaxf(m0s, ml0), mn1 = fmaxf(m1s, ml1);
        float al0 = __expf(m0s - mn0), al1 = __expf(m1s - mn1);
        m0s = mn0; m1s = mn1;

        float rs0 = 0.f, rs1 = 0.f;
#pragma unroll
        for (int nt = 0; nt < 8; nt++) {
            s[nt][0] = __expf(s[nt][0] - mn0);
            s[nt][1] = __expf(s[nt][1] - mn0);
            s[nt][2] = __expf(s[nt][2] - mn1);
            s[nt][3] = __expf(s[nt][3] - mn1);
            rs0 += s[nt][0] + s[nt][1];
            rs1 += s[nt][2] + s[nt][3];
        }
        rs0 += __shfl_xor_sync(0xffffffffu, rs0, 1);
        rs0 += __shfl_xor_sync(0xffffffffu, rs0, 2);
        rs1 += __shfl_xor_sync(0xffffffffu, rs1, 1);
        rs1 += __shfl_xor_sync(0xffffffffu, rs1, 2);
        l0 = l0 * al0 + rs0;
        l1 = l1 * al1 + rs1;
#pragma unroll
        for (int nt = 0; nt < 8; nt++) {
            acc_o[nt][0] *= al0; acc_o[nt][1] *= al0;
            acc_o[nt][2] *= al1; acc_o[nt][3] *= al1;
        }

        // ---- P -> bf16 hi/lo A-fragments (C->A fragment identity)
        unsigned ph[4][4], pl[4][4];
#pragma unroll
        for (int c = 0; c < 4; c++) {
            cvt_pair(s[2 * c][0],     s[2 * c][1],     ph[c][0], pl[c][0]);
            cvt_pair(s[2 * c][2],     s[2 * c][3],     ph[c][1], pl[c][1]);
            cvt_pair(s[2 * c + 1][0], s[2 * c + 1][1], ph[c][2], pl[c][2]);
            cvt_pair(s[2 * c + 1][2], s[2 * c + 1][3], ph[c][3], pl[c][3]);
        }

        // ---- O += P V (bf16x3)
#pragma unroll
        for (int c = 0; c < 4; c++) {
#pragma unroll
            for (int nt = 0; nt < 8; nt++) {
                int off = (nt * 8 + qr) * 36 + c * 8 + (lane & 3);
                bh[nt][0] = s_kv[2 * KVW + off];  bh[nt][1] = s_kv[2 * KVW + off + 4];
                bl[nt][0] = s_kv[3 * KVW + off];  bl[nt][1] = s_kv[3 * KVW + off + 4];
            }
#pragma unroll
            for (int nt = 0; nt < 8; nt++) MMA_BF16(acc_o[nt], ph[c], bh[nt]);
#pragma unroll
            for (int nt = 0; nt < 8; nt++) MMA_BF16(acc_o[nt], ph[c], bl[nt]);
#pragma unroll
            for (int nt = 0; nt < 8; nt++) MMA_BF16(acc_o[nt], pl[c], bh[nt]);
        }
        __syncthreads();   // protect smem before next iteration's cp.async
    }

    // ---- epilogue: normalize and write concat layout [b][t][h*64+e]
    const float i0 = 1.f / l0, i1 = 1.f / l1;
    float* op = att + (long long)(z >> 4) * Tn * Dn + (z & 15) * HDn;
#pragma unroll
    for (int nt = 0; nt < 8; nt++) {
        float2 v0 = make_float2(acc_o[nt][0] * i0, acc_o[nt][1] * i0);
        float2 v1 = make_float2(acc_o[nt][2] * i1, acc_o[nt][3] * i1);
        *reinterpret_cast<float2*>(op + (long long)rga * Dn + nt * 8 + cb) = v0;
        *reinterpret_cast<float2*>(op + (long long)rgb * Dn + nt * 8 + cb) = v1;
    }
}

// ---------------------------------------------------------------------------
// LayerNorm over last dim (1024). One block (256 threads) per row.
// ---------------------------------------------------------------------------
__launch_bounds__(256)
__global__ void ln_kernel(const float* __restrict__ x,
                          const float* __restrict__ g,
                          const float* __restrict__ be,
                          float* __restrict__ out)
{
    long long row = blockIdx.x;
    const float* xr = x + row * Dn;
    float* outr = out + row * Dn;
    int tid = threadIdx.x;

    float v[4];
    float s = 0.f;
#pragma unroll
    for (int i = 0; i < 4; i++) { v[i] = xr[tid + 256 * i]; s += v[i]; }

    __shared__ float red[8];
    __shared__ float sh_mu, sh_rstd;

#pragma unroll
    for (int o = 16; o > 0; o >>= 1) s += __shfl_xor_sync(0xffffffffu, s, o);
    if ((tid & 31) == 0) red[tid >> 5] = s;
    __syncthreads();
    if (tid == 0) {
        float t = 0.f;
        for (int i = 0; i < 8; i++) t += red[i];
        sh_mu = t * (1.0f / Dn);
    }
    __syncthreads();
    float mu = sh_mu;

    float ss = 0.f;
#pragma unroll
    for (int i = 0; i < 4; i++) { float d = v[i] - mu; ss += d * d; }
#pragma unroll
    for (int o = 16; o > 0; o >>= 1) ss += __shfl_xor_sync(0xffffffffu, ss, o);
    if ((tid & 31) == 0) red[tid >> 5] = ss;
    __syncthreads();
    if (tid == 0) {
        float t = 0.f;
        for (int i = 0; i < 8; i++) t += red[i];
        sh_rstd = rsqrtf(t * (1.0f / Dn) + 1e-5f);
    }
    __syncthreads();
    float rstd = sh_rstd;

#pragma unroll
    for (int i = 0; i < 4; i++) {
        int c = tid + 256 * i;
        outr[c] = (v[i] - mu) * rstd * g[c] + be[c];
    }
}

// ---------------------------------------------------------------------------
extern "C" void kernel_launch(void* const* d_in, const int* in_sizes, int n_in,
                              void* d_out, int out_size)
{
    const float* x   = (const float*)d_in[0];
    const float* Wq  = (const float*)d_in[1];
    const float* Wk  = (const float*)d_in[2];
    const float* Wv  = (const float*)d_in[3];
    const float* Wo  = (const float*)d_in[4];
    const float* bo  = (const float*)d_in[5];
    const float* W1  = (const float*)d_in[6];
    const float* b1  = (const float*)d_in[7];
    const float* W2  = (const float*)d_in[8];
    const float* b2  = (const float*)d_in[9];
    const float* g1  = (const float*)d_in[10];
    const float* be1 = (const float*)d_in[11];
    const float* g2  = (const float*)d_in[12];
    const float* be2 = (const float*)d_in[13];
    float* out = (float*)d_out;

    float *h1, *qkv, *att, *x2, *h2, *mid;
    __nv_bfloat16 *khi, *klo, *vthi, *vtlo;
    __nv_bfloat16 *wqkvhi, *wqkvlo, *wohi, *wolo, *w1hi, *w1lo, *w2hi, *w2lo;
    cudaGetSymbolAddress((void**)&h1,   g_h1);
    cudaGetSymbolAddress((void**)&qkv,  g_qkv);
    cudaGetSymbolAddress((void**)&khi,  g_khi);
    cudaGetSymbolAddress((void**)&klo,  g_klo);
    cudaGetSymbolAddress((void**)&vthi, g_vthi);
    cudaGetSymbolAddress((void**)&vtlo, g_vtlo);
    cudaGetSymbolAddress((void**)&att,  g_att);
    cudaGetSymbolAddress((void**)&x2,   g_x2);
    cudaGetSymbolAddress((void**)&h2,   g_h2);
    cudaGetSymbolAddress((void**)&mid,  g_mid);
    cudaGetSymbolAddress((void**)&wqkvhi, g_wqkvhi);
    cudaGetSymbolAddress((void**)&wqkvlo, g_wqkvlo);
    cudaGetSymbolAddress((void**)&wohi, g_wohi);
    cudaGetSymbolAddress((void**)&wolo, g_wolo);
    cudaGetSymbolAddress((void**)&w1hi, g_w1hi);
    cudaGetSymbolAddress((void**)&w1lo, g_w1lo);
    cudaGetSymbolAddress((void**)&w2hi, g_w2hi);
    cudaGetSymbolAddress((void**)&w2lo, g_w2lo);

    dim3 blk(256);
    dim3 tblk(32, 8);

    // ---- weight pre-split/transpose
    split_transpose<<<dim3(HDn / 32, Dn / 32, Hn), tblk>>>(
        Wq, wqkvhi + 0 * Dn * HDn, wqkvlo + 0 * Dn * HDn,
        HDn, (long long)Dn * HDn, Dn, (long long)192 * Dn);
    split_transpose<<<dim3(HDn / 32, Dn / 32, Hn), tblk>>>(
        Wk, wqkvhi + 1 * Dn * HDn, wqkvlo + 1 * Dn * HDn,
        HDn, (long long)Dn * HDn, Dn, (long long)192 * Dn);
    split_transpose<<<dim3(HDn / 32, Dn / 32, Hn), tblk>>>(
        Wv, wqkvhi + 2 * Dn * HDn, wqkvlo + 2 * Dn * HDn,
        HDn, (long long)Dn * HDn, Dn, (long long)192 * Dn);
    split_transpose<<<dim3(Dn / 32, Dn / 32, 1), tblk>>>(
        Wo, wohi, wolo, Dn, 0LL, Dn, 0LL);
    split_transpose<<<dim3(4 * Dn / 32, Dn / 32, 1), tblk>>>(
        W1, w1hi, w1lo, 4 * Dn, 0LL, Dn, 0LL);
    split_transpose<<<dim3(Dn / 32, 4 * Dn / 32, 1), tblk>>>(
        W2, w2hi, w2lo, Dn, 0LL, 4 * Dn, 0LL);

    // ---- LN1
    ln_kernel<<<ROWS, blk>>>(x, g1, be1, h1);

    // ---- fused QKV: qkv[z][T][192] = h1(b) @ wqkvT(h)^T ; z = b*H + h
    {
        dim3 grd(192 / 64, Tn / 128, ZHD);
        gemm_bf16x3<0><<<grd, blk>>>(
            h1, wqkvhi, wqkvlo, qkv, nullptr, nullptr,
            Tn, 192, Dn, Dn, Dn, 192, 1.0f,
            (long long)Tn * Dn, Hn, 0LL, 1,
            0LL, 1, (long long)192 * Dn, Hn,
            (long long)Tn * 192, 1, 0LL, 1);
    }

    // ---- K split + V transpose-split (flash operands)
    {
        long long krows = (long long)ZHD * Tn;
        int total = (int)(krows * (HDn / 4));
        split_copy<<<(total + 255) / 256, blk>>>(qkv + 64, khi, klo, krows, HDn, 192);
        split_transpose<<<dim3(HDn / 32, Tn / 32, ZHD), tblk>>>(
            qkv + 128, vthi, vtlo, 192, (long long)Tn * 192, Tn, (long long)HDn * Tn);
    }

    // ---- flash attention (fused QK^T + causal softmax + PV)
    flash_kernel<<<dim3(Tn / 128, ZHD), blk>>>(qkv, khi, klo, vthi, vtlo, att);

    // ---- O projection + bias + residual: x2 = x + att @ Wo + bo
    {
        dim3 grd(Dn / 64, ROWS / 128, 1);
        gemm_bf16x3<2><<<grd, blk>>>(
            att, wohi, wolo, x2, bo, x,
            ROWS, Dn, Dn, Dn, Dn, Dn, 1.0f,
            0LL, 1, 0LL, 1, 0LL, 1, 0LL, 1, 0LL, 1, 0LL, 1);
    }

    // ---- LN2
    ln_kernel<<<ROWS, blk>>>(x2, g2, be2, h2);

    // ---- FFN1: mid = relu(h2 @ W1 + b1)
    {
        dim3 grd(4 * Dn / 64, ROWS / 128, 1);
        gemm_bf16x3<1><<<grd, blk>>>(
            h2, w1hi, w1lo, mid, b1, nullptr,
            ROWS, 4 * Dn, Dn, Dn, Dn, 4 * Dn, 1.0f,
            0LL, 1, 0LL, 1, 0LL, 1, 0LL, 1, 0LL, 1, 0LL, 1);
    }

    // ---- FFN2: out = x2 + mid @ W2 + b2
    {
        dim3 grd(Dn / 64, ROWS / 128, 1);
        gemm_bf16x3<2><<<grd, blk>>>(
            mid, w2hi, w2lo, out, b2, x2,
            ROWS, Dn, 4 * Dn, 4 * Dn, 4 * Dn, Dn, 1.0f,
            0LL, 1, 0LL, 1, 0LL, 1, 0LL, 1, 0LL, 1, 0LL, 1);
    }
}

// round 5
// speedup vs baseline: 2.4625x; 1.1461x over previous
#include <cuda_runtime.h>
#include <cuda_bf16.h>

// Problem constants
#define Tn   2048
#define Dn   1024
#define Hn   16
#define HDn  64
#define Bn   2
#define ROWS (Bn * Tn)   // 4096
#define ZHD  (Bn * Hn)   // 32

// ---------------- scratch (static device globals; no allocations) ----------
__device__ __nv_bfloat16 g_h1hi[ROWS * Dn],  g_h1lo[ROWS * Dn];
__device__ float g_qkv[ZHD * Tn * 192];                       // fused q|k|v per (b,h)
__device__ __nv_bfloat16 g_khi [ZHD * Tn * HDn], g_klo [ZHD * Tn * HDn];
__device__ __nv_bfloat16 g_vthi[ZHD * Tn * HDn], g_vtlo[ZHD * Tn * HDn];
__device__ __nv_bfloat16 g_atthi[ROWS * Dn], g_attlo[ROWS * Dn];
__device__ float g_x2 [ROWS * Dn];
__device__ __nv_bfloat16 g_h2hi[ROWS * Dn],  g_h2lo[ROWS * Dn];
__device__ __nv_bfloat16 g_midhi[ROWS * 4 * Dn], g_midlo[ROWS * 4 * Dn];
__device__ __nv_bfloat16 g_wqkvhi[Hn * 256 * Dn], g_wqkvlo[Hn * 256 * Dn];  // padded 192->256
__device__ __nv_bfloat16 g_wohi[Dn * Dn],       g_wolo[Dn * Dn];
__device__ __nv_bfloat16 g_w1hi[Dn * 4 * Dn],   g_w1lo[Dn * 4 * Dn];
__device__ __nv_bfloat16 g_w2hi[4 * Dn * Dn],   g_w2lo[4 * Dn * Dn];

// ---------------------------------------------------------------------------
__device__ __forceinline__ void split1(float v, __nv_bfloat16& h, __nv_bfloat16& l) {
    h = __float2bfloat16(v);
    l = __float2bfloat16(v - __bfloat162float(h));
}

__device__ __forceinline__ void cvt_pair(float a, float b, unsigned& hi, unsigned& lo) {
    __nv_bfloat16 ha, la, hb, lb;
    split1(a, ha, la);
    split1(b, hb, lb);
    hi = ((unsigned)__bfloat16_as_ushort(hb) << 16) | (unsigned)__bfloat16_as_ushort(ha);
    lo = ((unsigned)__bfloat16_as_ushort(lb) << 16) | (unsigned)__bfloat16_as_ushort(la);
}

#define MMA_BF16(d, a, b) \
    asm volatile("mma.sync.aligned.m16n8k16.row.col.f32.bf16.bf16.f32 " \
                 "{%0,%1,%2,%3},{%4,%5,%6,%7},{%8,%9},{%0,%1,%2,%3};\n" \
                 : "+f"(d[0]), "+f"(d[1]), "+f"(d[2]), "+f"(d[3]) \
                 : "r"(a[0]), "r"(a[1]), "r"(a[2]), "r"(a[3]), "r"(b[0]), "r"(b[1]))

__device__ __forceinline__ unsigned smem_u32(const void* p) {
    return (unsigned)__cvta_generic_to_shared(p);
}
__device__ __forceinline__ void cp16(unsigned dst, const void* src) {
    asm volatile("cp.async.cg.shared.global [%0],[%1],16;\n" :: "r"(dst), "l"(src));
}

// ---------------------------------------------------------------------------
// split+transpose: in [z][R][C] fp32 (row stride ldin) -> out [z][C][R] bf16 hi/lo
// ---------------------------------------------------------------------------
__global__ void split_transpose(const float* __restrict__ in,
                                __nv_bfloat16* __restrict__ ohi,
                                __nv_bfloat16* __restrict__ olo,
                                int ldin, long long sIn, int ldout, long long sOut)
{
    __shared__ float t[32][33];
    int z = blockIdx.z;
    in  += (long long)z * sIn;
    ohi += (long long)z * sOut;
    olo += (long long)z * sOut;
    int c0 = blockIdx.x * 32, r0 = blockIdx.y * 32;
    int tx = threadIdx.x, ty = threadIdx.y;
#pragma unroll
    for (int i = 0; i < 32; i += 8)
        t[ty + i][tx] = in[(long long)(r0 + ty + i) * ldin + c0 + tx];
    __syncthreads();
#pragma unroll
    for (int i = 0; i < 32; i += 8) {
        float v = t[tx][ty + i];
        __nv_bfloat16 h, l;
        split1(v, h, l);
        long long o = (long long)(c0 + ty + i) * ldout + r0 + tx;
        ohi[o] = h;
        olo[o] = l;
    }
}

// split copy (no transpose)
__global__ void split_copy(const float* __restrict__ in,
                           __nv_bfloat16* __restrict__ ohi,
                           __nv_bfloat16* __restrict__ olo,
                           long long rows, int C, int ldin)
{
    long long i = (long long)blockIdx.x * blockDim.x + threadIdx.x;
    long long total = rows * (C / 4);
    if (i >= total) return;
    long long r = i / (C / 4);
    int c = (int)(i % (C / 4)) * 4;
    float4 v = *reinterpret_cast<const float4*>(&in[r * ldin + c]);
    unsigned h0, l0, h1, l1;
    cvt_pair(v.x, v.y, h0, l0);
    cvt_pair(v.z, v.w, h1, l1);
    long long o = r * C + c;
    *reinterpret_cast<unsigned*>(&ohi[o])     = h0;
    *reinterpret_cast<unsigned*>(&ohi[o + 2]) = h1;
    *reinterpret_cast<unsigned*>(&olo[o])     = l0;
    *reinterpret_cast<unsigned*>(&olo[o + 2]) = l1;
}

// ---------------------------------------------------------------------------
// GEMM v2 (bf16x3, both operands pre-split): C = A @ B^T (+epi)
//   A bf16 hi/lo [M,K] (lda); B bf16 hi/lo [N,K] (ldb)
//   EPI: 0 -> fp32 C (store guard cc<N); 1 -> bias+relu, bf16 hi/lo C;
//        2 -> bias+residual, fp32 C
// BM=128, BN=128, BK=32, 256 thr (warps 2m x 4n, warp tile 64x32),
// 2-stage cp.async double buffer. Dynamic smem: 2 * 10240 words = 80 KB.
// ---------------------------------------------------------------------------
template <int EPI>
__launch_bounds__(256)
__global__ void gemm2(const __nv_bfloat16* __restrict__ Ahi,
                      const __nv_bfloat16* __restrict__ Alo,
                      const __nv_bfloat16* __restrict__ Bhi,
                      const __nv_bfloat16* __restrict__ Blo,
                      float* __restrict__ C,
                      __nv_bfloat16* __restrict__ Chi,
                      __nv_bfloat16* __restrict__ Clo,
                      const float* __restrict__ bias,
                      const float* __restrict__ res,
                      int N, int K, int lda, int ldb, int ldc,
                      long long sA1, int dA, long long sA2, int mA,
                      long long sB1, int dB, long long sB2, int mB,
                      long long sC1, int dC, long long sC2, int mC)
{
    extern __shared__ unsigned sm[];
    // stage layout (words): AHI 0..2559, ALO 2560.., BHI 5120.., BLO 7680..
    const int m0 = blockIdx.y * 128;
    const int n0 = blockIdx.x * 128;

    const int z = blockIdx.z;
    {
        const long long aoff = (long long)(z / dA) * sA1 + (long long)(z % mA) * sA2;
        Ahi += aoff; Alo += aoff;
        const long long boff = (long long)(z / dB) * sB1 + (long long)(z % mB) * sB2;
        Bhi += boff; Blo += boff;
        const long long coff = (long long)(z / dC) * sC1 + (long long)(z % mC) * sC2;
        if (EPI == 1) { Chi += coff; Clo += coff; }
        else          { C += coff; }
        if (EPI == 2) res += coff;
    }

    const int tid  = threadIdx.x;
    const int lane = tid & 31;
    const int w    = tid >> 5;
    const int wm   = (w & 1) * 64;
    const int wn   = (w >> 1) * 32;
    const int nk   = K / 32;

    float acc[4][4][4];
#pragma unroll
    for (int mt = 0; mt < 4; mt++)
#pragma unroll
        for (int nt = 0; nt < 4; nt++)
#pragma unroll
            for (int j = 0; j < 4; j++) acc[mt][nt][j] = 0.f;

    // ---- stage loader
    auto load_stage = [&](int st, int kt) {
        unsigned* sb = sm + st * 10240;
        const int k0 = kt * 32;
#pragma unroll
        for (int l = 0; l < 2; l++) {
            int c = tid * 2 + l;                 // 0..511
            int row = c >> 2;
            int cw  = (c & 3) * 4;               // word offset in row
            int ke  = (c & 3) * 8;               // element offset in row
            unsigned d = smem_u32(sb + row * 20 + cw);
            cp16(d,             Ahi + (long long)(m0 + row) * lda + k0 + ke);
            cp16(d + 2560 * 4,  Alo + (long long)(m0 + row) * lda + k0 + ke);
            cp16(d + 5120 * 4,  Bhi + (long long)(n0 + row) * ldb + k0 + ke);
            cp16(d + 7680 * 4,  Blo + (long long)(n0 + row) * ldb + k0 + ke);
        }
        asm volatile("cp.async.commit_group;");
    };

    load_stage(0, 0);

    for (int kt = 0; kt < nk; kt++) {
        if (kt + 1 < nk) {
            load_stage((kt + 1) & 1, kt + 1);
            asm volatile("cp.async.wait_group 1;");
        } else {
            asm volatile("cp.async.wait_group 0;");
        }
        __syncthreads();

        const unsigned* sb = sm + (kt & 1) * 10240;
#pragma unroll
        for (int s = 0; s < 2; s++) {
            const int kb = (lane & 3) + s * 8;
            unsigned ah[4][4], al[4][4], bh[4][2], bl[4][2];
#pragma unroll
            for (int mt = 0; mt < 4; mt++) {
                const int r = wm + mt * 16 + (lane >> 2);
                ah[mt][0] = sb[r * 20 + kb];
                ah[mt][1] = sb[(r + 8) * 20 + kb];
                ah[mt][2] = sb[r * 20 + kb + 4];
                ah[mt][3] = sb[(r + 8) * 20 + kb + 4];
                al[mt][0] = sb[2560 + r * 20 + kb];
                al[mt][1] = sb[2560 + (r + 8) * 20 + kb];
                al[mt][2] = sb[2560 + r * 20 + kb + 4];
                al[mt][3] = sb[2560 + (r + 8) * 20 + kb + 4];
            }
#pragma unroll
            for (int nt = 0; nt < 4; nt++) {
                const int rn = wn + nt * 8 + (lane >> 2);
                bh[nt][0] = sb[5120 + rn * 20 + kb];
                bh[nt][1] = sb[5120 + rn * 20 + kb + 4];
                bl[nt][0] = sb[7680 + rn * 20 + kb];
                bl[nt][1] = sb[7680 + rn * 20 + kb + 4];
            }
            // pass-major: hi*hi, hi*lo, lo*hi
#pragma unroll
            for (int mt = 0; mt < 4; mt++)
#pragma unroll
                for (int nt = 0; nt < 4; nt++) MMA_BF16(acc[mt][nt], ah[mt], bh[nt]);
#pragma unroll
            for (int mt = 0; mt < 4; mt++)
#pragma unroll
                for (int nt = 0; nt < 4; nt++) MMA_BF16(acc[mt][nt], ah[mt], bl[nt]);
#pragma unroll
            for (int mt = 0; mt < 4; mt++)
#pragma unroll
                for (int nt = 0; nt < 4; nt++) MMA_BF16(acc[mt][nt], al[mt], bh[nt]);
        }
        __syncthreads();
    }

    // ---- epilogue
#pragma unroll
    for (int mt = 0; mt < 4; mt++)
#pragma unroll
        for (int nt = 0; nt < 4; nt++) {
            const float* a4 = acc[mt][nt];
            const long long r0 = m0 + wm + mt * 16 + (lane >> 2);
            const long long r1 = r0 + 8;
            const int cc = n0 + wn + nt * 8 + (lane & 3) * 2;
            if (EPI == 0) {
                if (cc < N) {
                    *reinterpret_cast<float2*>(&C[r0 * ldc + cc]) = make_float2(a4[0], a4[1]);
                    *reinterpret_cast<float2*>(&C[r1 * ldc + cc]) = make_float2(a4[2], a4[3]);
                }
            } else if (EPI == 1) {
                float2 bv = *reinterpret_cast<const float2*>(&bias[cc]);
                float v0 = fmaxf(a4[0] + bv.x, 0.f);
                float v1 = fmaxf(a4[1] + bv.y, 0.f);
                float v2 = fmaxf(a4[2] + bv.x, 0.f);
                float v3 = fmaxf(a4[3] + bv.y, 0.f);
                unsigned hw, lw;
                cvt_pair(v0, v1, hw, lw);
                *reinterpret_cast<unsigned*>(&Chi[r0 * ldc + cc]) = hw;
                *reinterpret_cast<unsigned*>(&Clo[r0 * ldc + cc]) = lw;
                cvt_pair(v2, v3, hw, lw);
                *reinterpret_cast<unsigned*>(&Chi[r1 * ldc + cc]) = hw;
                *reinterpret_cast<unsigned*>(&Clo[r1 * ldc + cc]) = lw;
            } else {
                float2 bv = *reinterpret_cast<const float2*>(&bias[cc]);
                float2 q0 = *reinterpret_cast<const float2*>(&res[r0 * ldc + cc]);
                float2 q1 = *reinterpret_cast<const float2*>(&res[r1 * ldc + cc]);
                *reinterpret_cast<float2*>(&C[r0 * ldc + cc]) =
                    make_float2(a4[0] + bv.x + q0.x, a4[1] + bv.y + q0.y);
                *reinterpret_cast<float2*>(&C[r1 * ldc + cc]) =
                    make_float2(a4[2] + bv.x + q1.x, a4[3] + bv.y + q1.y);
            }
        }
}

// ---------------------------------------------------------------------------
// Flash attention (unchanged math from round 3); epilogue writes att bf16 hi/lo.
// grid = (Tn/128, ZHD), block = 256.
// ---------------------------------------------------------------------------
__launch_bounds__(256)
__global__ void flash_kernel(const float* __restrict__ qkv,
                             const __nv_bfloat16* __restrict__ Khi,
                             const __nv_bfloat16* __restrict__ Klo,
                             const __nv_bfloat16* __restrict__ Vhi,
                             const __nv_bfloat16* __restrict__ Vlo,
                             __nv_bfloat16* __restrict__ atthi,
                             __nv_bfloat16* __restrict__ attlo)
{
    constexpr int KVW = 64 * 36;
    __shared__ __align__(16) unsigned s_kv[4 * KVW];

    const int z  = blockIdx.y;
    const int m0 = blockIdx.x * 128;
    const int tid = threadIdx.x, lane = tid & 31, w = tid >> 5;
    const int qr = lane >> 2;
    const int cb = (lane & 3) * 2;

    unsigned qh[4][4], ql[4][4];
    {
        float* sQ = (float*)s_kv;
        const float* Qg = qkv + (long long)z * Tn * 192 + (long long)m0 * 192;
#pragma unroll
        for (int i = 0; i < 8; i++) {
            int idx = tid + 256 * i;
            int r = idx >> 4, c4 = idx & 15;
            float4 v = *reinterpret_cast<const float4*>(Qg + (long long)r * 192 + c4 * 4);
            *reinterpret_cast<float4*>(sQ + r * 68 + c4 * 4) = v;
        }
        __syncthreads();
        const int ra = w * 16 + qr;
        const float sc = 0.03125f;
#pragma unroll
        for (int c = 0; c < 4; c++) {
            float p0 = sQ[ra * 68 + c * 16 + cb]           * sc;
            float p1 = sQ[ra * 68 + c * 16 + cb + 1]       * sc;
            float p2 = sQ[(ra + 8) * 68 + c * 16 + cb]     * sc;
            float p3 = sQ[(ra + 8) * 68 + c * 16 + cb + 1] * sc;
            float p4 = sQ[ra * 68 + c * 16 + cb + 8]       * sc;
            float p5 = sQ[ra * 68 + c * 16 + cb + 9]       * sc;
            float p6 = sQ[(ra + 8) * 68 + c * 16 + cb + 8] * sc;
            float p7 = sQ[(ra + 8) * 68 + c * 16 + cb + 9] * sc;
            cvt_pair(p0, p1, qh[c][0], ql[c][0]);
            cvt_pair(p2, p3, qh[c][1], ql[c][1]);
            cvt_pair(p4, p5, qh[c][2], ql[c][2]);
            cvt_pair(p6, p7, qh[c][3], ql[c][3]);
        }
        __syncthreads();
    }

    float m0s = -1e30f, m1s = -1e30f;
    float l0 = 0.f, l1 = 0.f;
    float acc_o[8][4];
#pragma unroll
    for (int nt = 0; nt < 8; nt++)
#pragma unroll
        for (int j = 0; j < 4; j++) acc_o[nt][j] = 0.f;

    const int nkb = blockIdx.x * 2 + 2;
    const long long kbaseK = (long long)z * Tn * HDn;
    const long long kbaseV = (long long)z * HDn * Tn;
    const int rga = m0 + w * 16 + qr;
    const int rgb = rga + 8;

    for (int it = 0; it < nkb; it++) {
        {
            const __nv_bfloat16* pKh = Khi + kbaseK + (long long)it * 64 * HDn;
            const __nv_bfloat16* pKl = Klo + kbaseK + (long long)it * 64 * HDn;
            const __nv_bfloat16* pVh = Vhi + kbaseV + it * 64;
            const __nv_bfloat16* pVl = Vlo + kbaseV + it * 64;
#pragma unroll
            for (int i = 0; i < 2; i++) {
                int idx = tid + 256 * i;
                int r = idx >> 3, s = idx & 7;
                unsigned doff = r * 36 + s * 4;
                cp16(smem_u32(s_kv + doff),            pKh + r * HDn + s * 8);
                cp16(smem_u32(s_kv + KVW + doff),      pKl + r * HDn + s * 8);
                cp16(smem_u32(s_kv + 2 * KVW + doff),  pVh + (long long)r * Tn + s * 8);
                cp16(smem_u32(s_kv + 3 * KVW + doff),  pVl + (long long)r * Tn + s * 8);
            }
            asm volatile("cp.async.commit_group;");
            asm volatile("cp.async.wait_group 0;");
        }
        __syncthreads();

        float s[8][4];
#pragma unroll
        for (int nt = 0; nt < 8; nt++)
#pragma unroll
            for (int j = 0; j < 4; j++) s[nt][j] = 0.f;

        unsigned bh[8][2], bl[8][2];
#pragma unroll
        for (int c = 0; c < 4; c++) {
#pragma unroll
            for (int nt = 0; nt < 8; nt++) {
                int off = (nt * 8 + qr) * 36 + c * 8 + (lane & 3);
                bh[nt][0] = s_kv[off];        bh[nt][1] = s_kv[off + 4];
                bl[nt][0] = s_kv[KVW + off];  bl[nt][1] = s_kv[KVW + off + 4];
            }
#pragma unroll
            for (int nt = 0; nt < 8; nt++) MMA_BF16(s[nt], qh[c], bh[nt]);
#pragma unroll
            for (int nt = 0; nt < 8; nt++) MMA_BF16(s[nt], qh[c], bl[nt]);
#pragma unroll
            for (int nt = 0; nt < 8; nt++) MMA_BF16(s[nt], ql[c], bh[nt]);
        }

        const int cg0 = it * 64 + cb;
        if (it * 64 + 63 > rga) {
#pragma unroll
            for (int nt = 0; nt < 8; nt++) {
                int cg = cg0 + nt * 8;
                if (cg > rga)     s[nt][0] = -1e30f;
                if (cg + 1 > rga) s[nt][1] = -1e30f;
                if (cg > rgb)     s[nt][2] = -1e30f;
                if (cg + 1 > rgb) s[nt][3] = -1e30f;
            }
        }

        float ml0 = -1e30f, ml1 = -1e30f;
#pragma unroll
        for (int nt = 0; nt < 8; nt++) {
            ml0 = fmaxf(ml0, fmaxf(s[nt][0], s[nt][1]));
            ml1 = fmaxf(ml1, fmaxf(s[nt][2], s[nt][3]));
        }
        ml0 = fmaxf(ml0, __shfl_xor_sync(0xffffffffu, ml0, 1));
        ml0 = fmaxf(ml0, __shfl_xor_sync(0xffffffffu, ml0, 2));
        ml1 = fmaxf(ml1, __shfl_xor_sync(0xffffffffu, ml1, 1));
        ml1 = fmaxf(ml1, __shfl_xor_sync(0xffffffffu, ml1, 2));
        float mn0 = fmaxf(m0s, ml0), mn1 = fmaxf(m1s, ml1);
        float al0 = __expf(m0s - mn0), al1 = __expf(m1s - mn1);
        m0s = mn0; m1s = mn1;

        float rs0 = 0.f, rs1 = 0.f;
#pragma unroll
        for (int nt = 0; nt < 8; nt++) {
            s[nt][0] = __expf(s[nt][0] - mn0);
            s[nt][1] = __expf(s[nt][1] - mn0);
            s[nt][2] = __expf(s[nt][2] - mn1);
            s[nt][3] = __expf(s[nt][3] - mn1);
            rs0 += s[nt][0] + s[nt][1];
            rs1 += s[nt][2] + s[nt][3];
        }
        rs0 += __shfl_xor_sync(0xffffffffu, rs0, 1);
        rs0 += __shfl_xor_sync(0xffffffffu, rs0, 2);
        rs1 += __shfl_xor_sync(0xffffffffu, rs1, 1);
        rs1 += __shfl_xor_sync(0xffffffffu, rs1, 2);
        l0 = l0 * al0 + rs0;
        l1 = l1 * al1 + rs1;
#pragma unroll
        for (int nt = 0; nt < 8; nt++) {
            acc_o[nt][0] *= al0; acc_o[nt][1] *= al0;
            acc_o[nt][2] *= al1; acc_o[nt][3] *= al1;
        }

        unsigned ph[4][4], pl[4][4];
#pragma unroll
        for (int c = 0; c < 4; c++) {
            cvt_pair(s[2 * c][0],     s[2 * c][1],     ph[c][0], pl[c][0]);
            cvt_pair(s[2 * c][2],     s[2 * c][3],     ph[c][1], pl[c][1]);
            cvt_pair(s[2 * c + 1][0], s[2 * c + 1][1], ph[c][2], pl[c][2]);
            cvt_pair(s[2 * c + 1][2], s[2 * c + 1][3], ph[c][3], pl[c][3]);
        }

#pragma unroll
        for (int c = 0; c < 4; c++) {
#pragma unroll
            for (int nt = 0; nt < 8; nt++) {
                int off = (nt * 8 + qr) * 36 + c * 8 + (lane & 3);
                bh[nt][0] = s_kv[2 * KVW + off];  bh[nt][1] = s_kv[2 * KVW + off + 4];
                bl[nt][0] = s_kv[3 * KVW + off];  bl[nt][1] = s_kv[3 * KVW + off + 4];
            }
#pragma unroll
            for (int nt = 0; nt < 8; nt++) MMA_BF16(acc_o[nt], ph[c], bh[nt]);
#pragma unroll
            for (int nt = 0; nt < 8; nt++) MMA_BF16(acc_o[nt], ph[c], bl[nt]);
#pragma unroll
            for (int nt = 0; nt < 8; nt++) MMA_BF16(acc_o[nt], pl[c], bh[nt]);
        }
        __syncthreads();
    }

    // ---- epilogue: normalize, split to bf16 hi/lo, concat layout [b][t][h*64+e]
    const float i0 = 1.f / l0, i1 = 1.f / l1;
    const long long obase = (long long)(z >> 4) * Tn * Dn + (z & 15) * HDn;
#pragma unroll
    for (int nt = 0; nt < 8; nt++) {
        unsigned hw, lw;
        cvt_pair(acc_o[nt][0] * i0, acc_o[nt][1] * i0, hw, lw);
        *reinterpret_cast<unsigned*>(&atthi[obase + (long long)rga * Dn + nt * 8 + cb]) = hw;
        *reinterpret_cast<unsigned*>(&attlo[obase + (long long)rga * Dn + nt * 8 + cb]) = lw;
        cvt_pair(acc_o[nt][2] * i1, acc_o[nt][3] * i1, hw, lw);
        *reinterpret_cast<unsigned*>(&atthi[obase + (long long)rgb * Dn + nt * 8 + cb]) = hw;
        *reinterpret_cast<unsigned*>(&attlo[obase + (long long)rgb * Dn + nt * 8 + cb]) = lw;
    }
}

// ---------------------------------------------------------------------------
// LayerNorm over last dim (1024), output pre-split bf16 hi/lo.
// ---------------------------------------------------------------------------
__launch_bounds__(256)
__global__ void ln_kernel(const float* __restrict__ x,
                          const float* __restrict__ g,
                          const float* __restrict__ be,
                          __nv_bfloat16* __restrict__ ohi,
                          __nv_bfloat16* __restrict__ olo)
{
    long long row = blockIdx.x;
    const float* xr = x + row * Dn;
    int tid = threadIdx.x;

    float v[4];
    float s = 0.f;
#pragma unroll
    for (int i = 0; i < 4; i++) { v[i] = xr[tid + 256 * i]; s += v[i]; }

    __shared__ float red[8];
    __shared__ float sh_mu, sh_rstd;

#pragma unroll
    for (int o = 16; o > 0; o >>= 1) s += __shfl_xor_sync(0xffffffffu, s, o);
    if ((tid & 31) == 0) red[tid >> 5] = s;
    __syncthreads();
    if (tid == 0) {
        float t = 0.f;
        for (int i = 0; i < 8; i++) t += red[i];
        sh_mu = t * (1.0f / Dn);
    }
    __syncthreads();
    float mu = sh_mu;

    float ss = 0.f;
#pragma unroll
    for (int i = 0; i < 4; i++) { float d = v[i] - mu; ss += d * d; }
#pragma unroll
    for (int o = 16; o > 0; o >>= 1) ss += __shfl_xor_sync(0xffffffffu, ss, o);
    if ((tid & 31) == 0) red[tid >> 5] = ss;
    __syncthreads();
    if (tid == 0) {
        float t = 0.f;
        for (int i = 0; i < 8; i++) t += red[i];
        sh_rstd = rsqrtf(t * (1.0f / Dn) + 1e-5f);
    }
    __syncthreads();
    float rstd = sh_rstd;

#pragma unroll
    for (int i = 0; i < 4; i++) {
        int c = tid + 256 * i;
        float val = (v[i] - mu) * rstd * g[c] + be[c];
        __nv_bfloat16 h, l;
        split1(val, h, l);
        ohi[row * Dn + c] = h;
        olo[row * Dn + c] = l;
    }
}

// ---------------------------------------------------------------------------
extern "C" void kernel_launch(void* const* d_in, const int* in_sizes, int n_in,
                              void* d_out, int out_size)
{
    const float* x   = (const float*)d_in[0];
    const float* Wq  = (const float*)d_in[1];
    const float* Wk  = (const float*)d_in[2];
    const float* Wv  = (const float*)d_in[3];
    const float* Wo  = (const float*)d_in[4];
    const float* bo  = (const float*)d_in[5];
    const float* W1  = (const float*)d_in[6];
    const float* b1  = (const float*)d_in[7];
    const float* W2  = (const float*)d_in[8];
    const float* b2  = (const float*)d_in[9];
    const float* g1  = (const float*)d_in[10];
    const float* be1 = (const float*)d_in[11];
    const float* g2  = (const float*)d_in[12];
    const float* be2 = (const float*)d_in[13];
    float* out = (float*)d_out;

    float *qkv, *x2;
    __nv_bfloat16 *h1hi, *h1lo, *h2hi, *h2lo, *atthi, *attlo, *midhi, *midlo;
    __nv_bfloat16 *khi, *klo, *vthi, *vtlo;
    __nv_bfloat16 *wqkvhi, *wqkvlo, *wohi, *wolo, *w1hi, *w1lo, *w2hi, *w2lo;
    cudaGetSymbolAddress((void**)&h1hi, g_h1hi);
    cudaGetSymbolAddress((void**)&h1lo, g_h1lo);
    cudaGetSymbolAddress((void**)&qkv,  g_qkv);
    cudaGetSymbolAddress((void**)&khi,  g_khi);
    cudaGetSymbolAddress((void**)&klo,  g_klo);
    cudaGetSymbolAddress((void**)&vthi, g_vthi);
    cudaGetSymbolAddress((void**)&vtlo, g_vtlo);
    cudaGetSymbolAddress((void**)&atthi, g_atthi);
    cudaGetSymbolAddress((void**)&attlo, g_attlo);
    cudaGetSymbolAddress((void**)&x2,   g_x2);
    cudaGetSymbolAddress((void**)&h2hi, g_h2hi);
    cudaGetSymbolAddress((void**)&h2lo, g_h2lo);
    cudaGetSymbolAddress((void**)&midhi, g_midhi);
    cudaGetSymbolAddress((void**)&midlo, g_midlo);
    cudaGetSymbolAddress((void**)&wqkvhi, g_wqkvhi);
    cudaGetSymbolAddress((void**)&wqkvlo, g_wqkvlo);
    cudaGetSymbolAddress((void**)&wohi, g_wohi);
    cudaGetSymbolAddress((void**)&wolo, g_wolo);
    cudaGetSymbolAddress((void**)&w1hi, g_w1hi);
    cudaGetSymbolAddress((void**)&w1lo, g_w1lo);
    cudaGetSymbolAddress((void**)&w2hi, g_w2hi);
    cudaGetSymbolAddress((void**)&w2lo, g_w2lo);

    // dynamic smem opt-in for gemm2 (80 KB > 48 KB static limit)
    const int GSMEM = 2 * 10240 * 4;
    cudaFuncSetAttribute(gemm2<0>, cudaFuncAttributeMaxDynamicSharedMemorySize, GSMEM);
    cudaFuncSetAttribute(gemm2<1>, cudaFuncAttributeMaxDynamicSharedMemorySize, GSMEM);
    cudaFuncSetAttribute(gemm2<2>, cudaFuncAttributeMaxDynamicSharedMemorySize, GSMEM);

    dim3 blk(256);
    dim3 tblk(32, 8);

    // ---- weight pre-split/transpose (wqkv padded to 256 rows/head)
    split_transpose<<<dim3(HDn / 32, Dn / 32, Hn), tblk>>>(
        Wq, wqkvhi + 0 * HDn * Dn, wqkvlo + 0 * HDn * Dn,
        HDn, (long long)Dn * HDn, Dn, (long long)256 * Dn);
    split_transpose<<<dim3(HDn / 32, Dn / 32, Hn), tblk>>>(
        Wk, wqkvhi + 1 * HDn * Dn, wqkvlo + 1 * HDn * Dn,
        HDn, (long long)Dn * HDn, Dn, (long long)256 * Dn);
    split_transpose<<<dim3(HDn / 32, Dn / 32, Hn), tblk>>>(
        Wv, wqkvhi + 2 * HDn * Dn, wqkvlo + 2 * HDn * Dn,
        HDn, (long long)Dn * HDn, Dn, (long long)256 * Dn);
    split_transpose<<<dim3(Dn / 32, Dn / 32, 1), tblk>>>(
        Wo, wohi, wolo, Dn, 0LL, Dn, 0LL);
    split_transpose<<<dim3(4 * Dn / 32, Dn / 32, 1), tblk>>>(
        W1, w1hi, w1lo, 4 * Dn, 0LL, Dn, 0LL);
    split_transpose<<<dim3(Dn / 32, 4 * Dn / 32, 1), tblk>>>(
        W2, w2hi, w2lo, Dn, 0LL, 4 * Dn, 0LL);

    // ---- LN1: x -> h1 (bf16 hi/lo)
    ln_kernel<<<ROWS, blk>>>(x, g1, be1, h1hi, h1lo);

    // ---- fused QKV: qkv[z][T][192] = h1(b) @ wqkvT(h)^T ; z = b*H + h
    gemm2<0><<<dim3(2, Tn / 128, ZHD), blk, GSMEM>>>(
        h1hi, h1lo, wqkvhi, wqkvlo, qkv, nullptr, nullptr, nullptr, nullptr,
        192, Dn, Dn, Dn, 192,
        (long long)Tn * Dn, Hn, 0LL, 1,          // A: per batch b = z/H
        0LL, 1, (long long)256 * Dn, Hn,         // B: per head h = z%H (padded)
        (long long)Tn * 192, 1, 0LL, 1);         // C: per z

    // ---- K split + V transpose-split (flash operands) from fp32 qkv
    {
        long long krows = (long long)ZHD * Tn;
        int total = (int)(krows * (HDn / 4));
        split_copy<<<(total + 255) / 256, blk>>>(qkv + 64, khi, klo, krows, HDn, 192);
        split_transpose<<<dim3(HDn / 32, Tn / 32, ZHD), tblk>>>(
            qkv + 128, vthi, vtlo, 192, (long long)Tn * 192, Tn, (long long)HDn * Tn);
    }

    // ---- flash attention -> att bf16 hi/lo (concat layout)
    flash_kernel<<<dim3(Tn / 128, ZHD), blk>>>(qkv, khi, klo, vthi, vtlo, atthi, attlo);

    // ---- O projection + bias + residual: x2 = x + att @ Wo + bo
    gemm2<2><<<dim3(Dn / 128, ROWS / 128, 1), blk, GSMEM>>>(
        atthi, attlo, wohi, wolo, x2, nullptr, nullptr, bo, x,
        Dn, Dn, Dn, Dn, Dn,
        0LL, 1, 0LL, 1, 0LL, 1, 0LL, 1, 0LL, 1, 0LL, 1);

    // ---- LN2: x2 -> h2 (bf16 hi/lo)
    ln_kernel<<<ROWS, blk>>>(x2, g2, be2, h2hi, h2lo);

    // ---- FFN1: mid = relu(h2 @ W1 + b1)  (bf16 hi/lo output)
    gemm2<1><<<dim3(4 * Dn / 128, ROWS / 128, 1), blk, GSMEM>>>(
        h2hi, h2lo, w1hi, w1lo, nullptr, midhi, midlo, b1, nullptr,
        4 * Dn, Dn, Dn, Dn, 4 * Dn,
        0LL, 1, 0LL, 1, 0LL, 1, 0LL, 1, 0LL, 1, 0LL, 1);

    // ---- FFN2: out = x2 + mid @ W2 + b2
    gemm2<2><<<dim3(Dn / 128, ROWS / 128, 1), blk, GSMEM>>>(
        midhi, midlo, w2hi, w2lo, out, nullptr, nullptr, b2, x2,
        Dn, 4 * Dn, 4 * Dn, 4 * Dn, Dn,
        0LL, 1, 0LL, 1, 0LL, 1, 0LL, 1, 0LL, 1, 0LL, 1);
}

// round 9
// speedup vs baseline: 4.5638x; 1.8533x over previous
#include <cuda_runtime.h>

// Problem constants
#define Tn   2048
#define Dn   1024
#define Hn   16
#define HDn  64
#define Bn   2
#define ROWS (Bn * Tn)   // 4096
#define ZHD  (Bn * Hn)   // 32

// ---------------- scratch (static device globals; no allocations) ----------
__device__ float g_h1 [ROWS * Dn];
__device__ float g_qkv[ZHD * Tn * 192];          // fused q|k|v per (b,h), tf32-rounded
__device__ float g_vt [ZHD * HDn * Tn];          // V^T per (b,h), tf32-rounded
__device__ float g_att[ROWS * Dn];
__device__ float g_x2 [ROWS * Dn];
__device__ float g_h2 [ROWS * Dn];
__device__ float g_mid[ROWS * 4 * Dn];
__device__ float g_wqkvT[Hn * 256 * Dn];         // [H][256][D], rows 192..255 stay zero
__device__ float g_woT [Dn * Dn];
__device__ float g_w1T [4 * Dn * Dn];            // [4D][D]
__device__ float g_w2T [4 * Dn * Dn];            // [D][4D]

// ---------------------------------------------------------------------------
__device__ __forceinline__ float rna(float x) {
    unsigned u;
    asm("cvt.rna.tf32.f32 %0, %1;" : "=r"(u) : "f"(x));
    return __uint_as_float(u);
}
__device__ __forceinline__ unsigned smem_u32(const void* p) {
    return (unsigned)__cvta_generic_to_shared(p);
}
__device__ __forceinline__ void cp16(unsigned dst, const void* src) {
    asm volatile("cp.async.cg.shared.global [%0],[%1],16;\n" :: "r"(dst), "l"(src));
}
#define CP_COMMIT()  asm volatile("cp.async.commit_group;" ::: "memory")
#define CP_WAIT(n)   asm volatile("cp.async.wait_group %0;" :: "n"(n) : "memory")

#define MMA_TF32(d, a, b) \
    asm volatile("mma.sync.aligned.m16n8k8.row.col.f32.tf32.tf32.f32 " \
                 "{%0,%1,%2,%3},{%4,%5,%6,%7},{%8,%9},{%0,%1,%2,%3};\n" \
                 : "+f"((d)[0]), "+f"((d)[1]), "+f"((d)[2]), "+f"((d)[3]) \
                 : "r"((a)[0]), "r"((a)[1]), "r"((a)[2]), "r"((a)[3]), \
                   "r"((b)[0]), "r"((b)[1]))

// ---------------------------------------------------------------------------
// transpose + tf32-round: in [z][R][C] fp32 (row stride ldin) -> out [z][C][R]
// ---------------------------------------------------------------------------
__global__ void transpose_rna(const float* __restrict__ in,
                              float* __restrict__ outp,
                              int ldin, long long sIn, int ldout, long long sOut)
{
    __shared__ float t[32][33];
    int z = blockIdx.z;
    in   += (long long)z * sIn;
    outp += (long long)z * sOut;
    int c0 = blockIdx.x * 32, r0 = blockIdx.y * 32;
    int tx = threadIdx.x, ty = threadIdx.y;
#pragma unroll
    for (int i = 0; i < 32; i += 8)
        t[ty + i][tx] = in[(long long)(r0 + ty + i) * ldin + c0 + tx];
    __syncthreads();
#pragma unroll
    for (int i = 0; i < 32; i += 8)
        outp[(long long)(c0 + ty + i) * ldout + r0 + tx] = rna(t[tx][ty + i]);
}

// ---------------------------------------------------------------------------
// gemm_tf32: single-pass TF32 GEMM. C = A @ B^T (+epi).
//   A fp32 [M,K] (tf32-rounded by producer); B fp32 [N,K] (rounded); fp32 acc.
//   EPI: 0 -> rounded fp32 C, guard cc<N; 1 -> bias+relu, rounded fp32 C;
//        2 -> bias+residual, exact fp32 C.
// BM=128, BN=128, BK=32, 256 thr (warps 2m x 4n, warp tile 64x32),
// 2-stage cp.async double buffer, XOR-swizzled smem (conflict-free).
// Dynamic smem: 2 * 8192 floats = 64 KB.
// ---------------------------------------------------------------------------
template <int EPI>
__launch_bounds__(256, 2)
__global__ void gemm_tf32(const float* __restrict__ A,
                          const float* __restrict__ B,
                          float* __restrict__ C,
                          const float* __restrict__ bias,
                          const float* __restrict__ res,
                          int N, int K, int lda, int ldb, int ldc,
                          long long sA1, int dA, long long sA2, int mA,
                          long long sB1, int dB, long long sB2, int mB,
                          long long sC1, int dC, long long sC2, int mC)
{
    extern __shared__ float sm[];      // stage s: A at s*8192, B at s*8192+4096

    const int m0 = blockIdx.y * 128;
    const int n0 = blockIdx.x * 128;

    const int z = blockIdx.z;
    A += (long long)(z / dA) * sA1 + (long long)(z % mA) * sA2;
    B += (long long)(z / dB) * sB1 + (long long)(z % mB) * sB2;
    const long long coff = (long long)(z / dC) * sC1 + (long long)(z % mC) * sC2;
    C += coff;
    if (EPI == 2) res += coff;

    const int tid  = threadIdx.x;
    const int lane = tid & 31;
    const int w    = tid >> 5;
    const int wm   = (w & 1) * 64;
    const int wn   = (w >> 1) * 32;
    const int q    = lane >> 2;
    const int kb   = lane & 3;
    const int nk   = K / 32;

    // loader constants: thread handles rows (tid>>3)+32i, float4 group tid&7
    const int lrow = tid >> 3;
    const int lg   = tid & 7;
    const unsigned lsw = ((unsigned)(lg * 4)) ^ ((unsigned)((lrow & 7) * 4));

    float acc[4][4][4];
#pragma unroll
    for (int mt = 0; mt < 4; mt++)
#pragma unroll
        for (int nt = 0; nt < 4; nt++)
#pragma unroll
            for (int j = 0; j < 4; j++) acc[mt][nt][j] = 0.f;

    auto load_stage = [&](int st, int kt) {
        float* sb = sm + st * 8192;
        const int k0 = kt * 32;
#pragma unroll
        for (int i = 0; i < 4; i++) {
            int row = lrow + 32 * i;
            unsigned off = row * 32 + lsw;
            cp16(smem_u32(sb + off),        A + (long long)(m0 + row) * lda + k0 + lg * 4);
            cp16(smem_u32(sb + 4096 + off), B + (long long)(n0 + row) * ldb + k0 + lg * 4);
        }
        CP_COMMIT();
    };

    load_stage(0, 0);

    for (int kt = 0; kt < nk; kt++) {
        if (kt + 1 < nk) {
            load_stage((kt + 1) & 1, kt + 1);
            CP_WAIT(1);
        } else {
            CP_WAIT(0);
        }
        __syncthreads();

        const unsigned* su = (const unsigned*)(sm + (kt & 1) * 8192);
        const unsigned qx = (unsigned)(q << 2);
#pragma unroll
        for (int s4 = 0; s4 < 4; s4++) {
            const int k8 = s4 * 8;
            const unsigned g0 = ((unsigned)k8 ^ qx) + kb;
            const unsigned g1 = ((unsigned)(k8 + 4) ^ qx) + kb;
            unsigned a[4][4], b[4][2];
#pragma unroll
            for (int mt = 0; mt < 4; mt++) {
                const int r = wm + mt * 16 + q;
                a[mt][0] = su[r * 32 + g0];
                a[mt][1] = su[(r + 8) * 32 + g0];
                a[mt][2] = su[r * 32 + g1];
                a[mt][3] = su[(r + 8) * 32 + g1];
            }
#pragma unroll
            for (int nt = 0; nt < 4; nt++) {
                const int rn = wn + nt * 8 + q;
                b[nt][0] = su[4096 + rn * 32 + g0];
                b[nt][1] = su[4096 + rn * 32 + g1];
            }
#pragma unroll
            for (int mt = 0; mt < 4; mt++)
#pragma unroll
                for (int nt = 0; nt < 4; nt++)
                    MMA_TF32(acc[mt][nt], a[mt], b[nt]);
        }
        __syncthreads();
    }

    // ---- epilogue
#pragma unroll
    for (int mt = 0; mt < 4; mt++)
#pragma unroll
        for (int nt = 0; nt < 4; nt++) {
            const float* a4 = acc[mt][nt];
            const long long r0 = m0 + wm + mt * 16 + q;
            const long long r1 = r0 + 8;
            const int cc = n0 + wn + nt * 8 + kb * 2;
            if (EPI == 0) {
                if (cc < N) {
                    *reinterpret_cast<float2*>(&C[r0 * ldc + cc]) =
                        make_float2(rna(a4[0]), rna(a4[1]));
                    *reinterpret_cast<float2*>(&C[r1 * ldc + cc]) =
                        make_float2(rna(a4[2]), rna(a4[3]));
                }
            } else if (EPI == 1) {
                float2 bv = *reinterpret_cast<const float2*>(&bias[cc]);
                *reinterpret_cast<float2*>(&C[r0 * ldc + cc]) =
                    make_float2(rna(fmaxf(a4[0] + bv.x, 0.f)),
                                rna(fmaxf(a4[1] + bv.y, 0.f)));
                *reinterpret_cast<float2*>(&C[r1 * ldc + cc]) =
                    make_float2(rna(fmaxf(a4[2] + bv.x, 0.f)),
                                rna(fmaxf(a4[3] + bv.y, 0.f)));
            } else {
                float2 bv = *reinterpret_cast<const float2*>(&bias[cc]);
                float2 q0 = *reinterpret_cast<const float2*>(&res[r0 * ldc + cc]);
                float2 q1 = *reinterpret_cast<const float2*>(&res[r1 * ldc + cc]);
                *reinterpret_cast<float2*>(&C[r0 * ldc + cc]) =
                    make_float2(a4[0] + bv.x + q0.x, a4[1] + bv.y + q0.y);
                *reinterpret_cast<float2*>(&C[r1 * ldc + cc]) =
                    make_float2(a4[2] + bv.x + q1.x, a4[3] + bv.y + q1.y);
            }
        }
}

// ---------------------------------------------------------------------------
// Flash attention, single-pass TF32. 128 query rows per block, 64-key tiles.
// K read directly from qkv (rounded); V^T from g_vt (rounded).
// P transposed C-frag -> A-frag via warp shuffles, RNA-rounded before PV MMA.
// grid = (Tn/128, ZHD), block = 256.
// ---------------------------------------------------------------------------
__launch_bounds__(256)
__global__ void flash_tf32(const float* __restrict__ qkv,
                           const float* __restrict__ vt,
                           float* __restrict__ att)
{
    __shared__ __align__(16) float s_u[8704];   // Q staging 128x68 / K(0..4095)+V(4096..8191)

    const int z  = blockIdx.y;
    const int m0 = blockIdx.x * 128;
    const int tid = threadIdx.x, lane = tid & 31, w = tid >> 5;
    const int q  = lane >> 2;
    const int kb = lane & 3;
    const unsigned qx = (unsigned)(q << 2);

    // ---- stage Q, extract tf32 A-fragments (scale 2^-5 folded; values pre-rounded)
    unsigned qf[8][4];
    {
        const float* Qg = qkv + (long long)z * Tn * 192 + (long long)m0 * 192;
#pragma unroll
        for (int i = 0; i < 8; i++) {
            int idx = tid + 256 * i;
            int r = idx >> 4, c4 = idx & 15;
            float4 v = *reinterpret_cast<const float4*>(Qg + (long long)r * 192 + c4 * 4);
            *reinterpret_cast<float4*>(s_u + r * 68 + c4 * 4) = v;
        }
        __syncthreads();
        const int ra = w * 16 + q;
        const float sc = 0.03125f;      // exact power of 2, keeps tf32-exactness
#pragma unroll
        for (int c = 0; c < 8; c++) {
            qf[c][0] = __float_as_uint(s_u[ra * 68 + c * 8 + kb] * sc);
            qf[c][1] = __float_as_uint(s_u[(ra + 8) * 68 + c * 8 + kb] * sc);
            qf[c][2] = __float_as_uint(s_u[ra * 68 + c * 8 + kb + 4] * sc);
            qf[c][3] = __float_as_uint(s_u[(ra + 8) * 68 + c * 8 + kb + 4] * sc);
        }
        __syncthreads();
    }

    float m0s = -1e30f, m1s = -1e30f;
    float l0 = 0.f, l1 = 0.f;
    float acc_o[8][4];
#pragma unroll
    for (int nt = 0; nt < 8; nt++)
#pragma unroll
        for (int j = 0; j < 4; j++) acc_o[nt][j] = 0.f;

    const int nkb = blockIdx.x * 2 + 2;
    const float* Kg = qkv + (long long)z * Tn * 192 + 64;
    const float* Vg = vt + (long long)z * HDn * Tn;
    const int rga = m0 + w * 16 + q;
    const int rgb = rga + 8;

    // loader constants: rows (tid>>4)+16i, float4 group tid&15
    const int lrow = tid >> 4;
    const int lg   = tid & 15;
    const unsigned lsw = ((unsigned)(lg * 4)) ^ ((unsigned)((lrow & 7) * 4));

    for (int it = 0; it < nkb; it++) {
        // ---- load K (64x64) and V^T (64x64) tiles, swizzled
        {
#pragma unroll
            for (int i = 0; i < 4; i++) {
                int row = lrow + 16 * i;
                unsigned off = row * 64 + lsw;
                cp16(smem_u32(s_u + off),
                     Kg + (long long)(it * 64 + row) * 192 + lg * 4);
                cp16(smem_u32(s_u + 4096 + off),
                     Vg + (long long)row * Tn + it * 64 + lg * 4);
            }
            CP_COMMIT();
            CP_WAIT(0);
        }
        __syncthreads();
        const unsigned* su = (const unsigned*)s_u;

        // ---- S = Q K^T (tf32)
        float s[8][4];
#pragma unroll
        for (int nt = 0; nt < 8; nt++)
#pragma unroll
            for (int j = 0; j < 4; j++) s[nt][j] = 0.f;

#pragma unroll
        for (int c = 0; c < 8; c++) {
            const int c8 = c * 8;
            const unsigned g0 = ((unsigned)c8 ^ qx) + kb;
            const unsigned g1 = ((unsigned)(c8 + 4) ^ qx) + kb;
#pragma unroll
            for (int nt = 0; nt < 8; nt++) {
                const int ro = (nt * 8 + q) * 64;
                unsigned bb[2] = { su[ro + g0], su[ro + g1] };
                MMA_TF32(s[nt], qf[c], bb);
            }
        }

        // ---- causal mask
        const int cb = kb * 2;
        if (it * 64 + 63 > rga) {
#pragma unroll
            for (int nt = 0; nt < 8; nt++) {
                int cg = it * 64 + nt * 8 + cb;
                if (cg > rga)     s[nt][0] = -1e30f;
                if (cg + 1 > rga) s[nt][1] = -1e30f;
                if (cg > rgb)     s[nt][2] = -1e30f;
                if (cg + 1 > rgb) s[nt][3] = -1e30f;
            }
        }

        // ---- online softmax
        float ml0 = -1e30f, ml1 = -1e30f;
#pragma unroll
        for (int nt = 0; nt < 8; nt++) {
            ml0 = fmaxf(ml0, fmaxf(s[nt][0], s[nt][1]));
            ml1 = fmaxf(ml1, fmaxf(s[nt][2], s[nt][3]));
        }
        ml0 = fmaxf(ml0, __shfl_xor_sync(0xffffffffu, ml0, 1));
        ml0 = fmaxf(ml0, __shfl_xor_sync(0xffffffffu, ml0, 2));
        ml1 = fmaxf(ml1, __shfl_xor_sync(0xffffffffu, ml1, 1));
        ml1 = fmaxf(ml1, __shfl_xor_sync(0xffffffffu, ml1, 2));
        float mn0 = fmaxf(m0s, ml0), mn1 = fmaxf(m1s, ml1);
        float al0 = __expf(m0s - mn0), al1 = __expf(m1s - mn1);
        m0s = mn0; m1s = mn1;

        float rs0 = 0.f, rs1 = 0.f;
#pragma unroll
        for (int nt = 0; nt < 8; nt++) {
            s[nt][0] = __expf(s[nt][0] - mn0);
            s[nt][1] = __expf(s[nt][1] - mn0);
            s[nt][2] = __expf(s[nt][2] - mn1);
            s[nt][3] = __expf(s[nt][3] - mn1);
            rs0 += s[nt][0] + s[nt][1];
            rs1 += s[nt][2] + s[nt][3];
        }
        rs0 += __shfl_xor_sync(0xffffffffu, rs0, 1);
        rs0 += __shfl_xor_sync(0xffffffffu, rs0, 2);
        rs1 += __shfl_xor_sync(0xffffffffu, rs1, 1);
        rs1 += __shfl_xor_sync(0xffffffffu, rs1, 2);
        l0 = l0 * al0 + rs0;
        l1 = l1 * al1 + rs1;
#pragma unroll
        for (int nt = 0; nt < 8; nt++) {
            acc_o[nt][0] *= al0; acc_o[nt][1] *= al0;
            acc_o[nt][2] *= al1; acc_o[nt][3] *= al1;
        }

        // ---- O += P V: shuffle-transpose P C-frag -> A-frag per key chunk
        const int src0 = (lane & ~3) | (kb >> 1);
        const int src1 = src0 + 2;
        const bool od = (kb & 1);
#pragma unroll
        for (int kc = 0; kc < 8; kc++) {
            float x0 = __shfl_sync(0xffffffffu, s[kc][0], src0);
            float x1 = __shfl_sync(0xffffffffu, s[kc][1], src0);
            float x2 = __shfl_sync(0xffffffffu, s[kc][2], src0);
            float x3 = __shfl_sync(0xffffffffu, s[kc][3], src0);
            float y0 = __shfl_sync(0xffffffffu, s[kc][0], src1);
            float y1 = __shfl_sync(0xffffffffu, s[kc][1], src1);
            float y2 = __shfl_sync(0xffffffffu, s[kc][2], src1);
            float y3 = __shfl_sync(0xffffffffu, s[kc][3], src1);
            unsigned pa[4];
            pa[0] = __float_as_uint(rna(od ? x1 : x0));
            pa[1] = __float_as_uint(rna(od ? x3 : x2));
            pa[2] = __float_as_uint(rna(od ? y1 : y0));
            pa[3] = __float_as_uint(rna(od ? y3 : y2));
            const int k8 = kc * 8;
            const unsigned g0 = ((unsigned)k8 ^ qx) + kb;
            const unsigned g1 = ((unsigned)(k8 + 4) ^ qx) + kb;
#pragma unroll
            for (int nt = 0; nt < 8; nt++) {
                const int ro = 4096 + (nt * 8 + q) * 64;
                unsigned bb[2] = { su[ro + g0], su[ro + g1] };
                MMA_TF32(acc_o[nt], pa, bb);
            }
        }
        __syncthreads();     // protect smem before next tile's cp.async
    }

    // ---- epilogue: normalize, round, write concat layout [b][t][h*64+e]
    const float i0 = 1.f / l0, i1 = 1.f / l1;
    float* op = att + (long long)(z >> 4) * Tn * Dn + (z & 15) * HDn;
    const int cb = kb * 2;
#pragma unroll
    for (int nt = 0; nt < 8; nt++) {
        *reinterpret_cast<float2*>(op + (long long)rga * Dn + nt * 8 + cb) =
            make_float2(rna(acc_o[nt][0] * i0), rna(acc_o[nt][1] * i0));
        *reinterpret_cast<float2*>(op + (long long)rgb * Dn + nt * 8 + cb) =
            make_float2(rna(acc_o[nt][2] * i1), rna(acc_o[nt][3] * i1));
    }
}

// ---------------------------------------------------------------------------
// LayerNorm over last dim (1024), output tf32-rounded fp32.
// ---------------------------------------------------------------------------
__launch_bounds__(256)
__global__ void ln_kernel(const float* __restrict__ x,
                          const float* __restrict__ g,
                          const float* __restrict__ be,
                          float* __restrict__ outp)
{
    long long row = blockIdx.x;
    const float* xr = x + row * Dn;
    int tid = threadIdx.x;

    float v[4];
    float s = 0.f;
#pragma unroll
    for (int i = 0; i < 4; i++) { v[i] = xr[tid + 256 * i]; s += v[i]; }

    __shared__ float red[8];
    __shared__ float sh_mu, sh_rstd;

#pragma unroll
    for (int o = 16; o > 0; o >>= 1) s += __shfl_xor_sync(0xffffffffu, s, o);
    if ((tid & 31) == 0) red[tid >> 5] = s;
    __syncthreads();
    if (tid == 0) {
        float t = 0.f;
        for (int i = 0; i < 8; i++) t += red[i];
        sh_mu = t * (1.0f / Dn);
    }
    __syncthreads();
    float mu = sh_mu;

    float ss = 0.f;
#pragma unroll
    for (int i = 0; i < 4; i++) { float d = v[i] - mu; ss += d * d; }
#pragma unroll
    for (int o = 16; o > 0; o >>= 1) ss += __shfl_xor_sync(0xffffffffu, ss, o);
    if ((tid & 31) == 0) red[tid >> 5] = ss;
    __syncthreads();
    if (tid == 0) {
        float t = 0.f;
        for (int i = 0; i < 8; i++) t += red[i];
        sh_rstd = rsqrtf(t * (1.0f / Dn) + 1e-5f);
    }
    __syncthreads();
    float rstd = sh_rstd;

#pragma unroll
    for (int i = 0; i < 4; i++) {
        int c = tid + 256 * i;
        outp[row * Dn + c] = rna((v[i] - mu) * rstd * g[c] + be[c]);
    }
}

// ---------------------------------------------------------------------------
extern "C" void kernel_launch(void* const* d_in, const int* in_sizes, int n_in,
                              void* d_out, int out_size)
{
    const float* x   = (const float*)d_in[0];
    const float* Wq  = (const float*)d_in[1];
    const float* Wk  = (const float*)d_in[2];
    const float* Wv  = (const float*)d_in[3];
    const float* Wo  = (const float*)d_in[4];
    const float* bo  = (const float*)d_in[5];
    const float* W1  = (const float*)d_in[6];
    const float* b1  = (const float*)d_in[7];
    const float* W2  = (const float*)d_in[8];
    const float* b2  = (const float*)d_in[9];
    const float* g1  = (const float*)d_in[10];
    const float* be1 = (const float*)d_in[11];
    const float* g2  = (const float*)d_in[12];
    const float* be2 = (const float*)d_in[13];
    float* out = (float*)d_out;

    float *h1, *qkv, *vt, *att, *x2, *h2, *mid;
    float *wqkvT, *woT, *w1T, *w2T;
    cudaGetSymbolAddress((void**)&h1,   g_h1);
    cudaGetSymbolAddress((void**)&qkv,  g_qkv);
    cudaGetSymbolAddress((void**)&vt,   g_vt);
    cudaGetSymbolAddress((void**)&att,  g_att);
    cudaGetSymbolAddress((void**)&x2,   g_x2);
    cudaGetSymbolAddress((void**)&h2,   g_h2);
    cudaGetSymbolAddress((void**)&mid,  g_mid);
    cudaGetSymbolAddress((void**)&wqkvT, g_wqkvT);
    cudaGetSymbolAddress((void**)&woT,  g_woT);
    cudaGetSymbolAddress((void**)&w1T,  g_w1T);
    cudaGetSymbolAddress((void**)&w2T,  g_w2T);

    const int GSMEM = 2 * 8192 * 4;    // 64 KB
    cudaFuncSetAttribute(gemm_tf32<0>, cudaFuncAttributeMaxDynamicSharedMemorySize, GSMEM);
    cudaFuncSetAttribute(gemm_tf32<1>, cudaFuncAttributeMaxDynamicSharedMemorySize, GSMEM);
    cudaFuncSetAttribute(gemm_tf32<2>, cudaFuncAttributeMaxDynamicSharedMemorySize, GSMEM);

    dim3 blk(256);
    dim3 tblk(32, 8);

    // ---- weight transposes (+ tf32 rounding); wqkvT rows 192..255 remain zero
    transpose_rna<<<dim3(HDn / 32, Dn / 32, Hn), tblk>>>(
        Wq, wqkvT + 0 * HDn * Dn, HDn, (long long)Dn * HDn, Dn, (long long)256 * Dn);
    transpose_rna<<<dim3(HDn / 32, Dn / 32, Hn), tblk>>>(
        Wk, wqkvT + 1 * HDn * Dn, HDn, (long long)Dn * HDn, Dn, (long long)256 * Dn);
    transpose_rna<<<dim3(HDn / 32, Dn / 32, Hn), tblk>>>(
        Wv, wqkvT + 2 * HDn * Dn, HDn, (long long)Dn * HDn, Dn, (long long)256 * Dn);
    transpose_rna<<<dim3(Dn / 32, Dn / 32, 1), tblk>>>(
        Wo, woT, Dn, 0LL, Dn, 0LL);
    transpose_rna<<<dim3(4 * Dn / 32, Dn / 32, 1), tblk>>>(
        W1, w1T, 4 * Dn, 0LL, Dn, 0LL);
    transpose_rna<<<dim3(Dn / 32, 4 * Dn / 32, 1), tblk>>>(
        W2, w2T, Dn, 0LL, 4 * Dn, 0LL);

    // ---- LN1: x -> h1 (rounded)
    ln_kernel<<<ROWS, blk>>>(x, g1, be1, h1);

    // ---- fused QKV: qkv[z][T][192] = h1(b) @ wqkvT(h)^T ; z = b*H + h
    gemm_tf32<0><<<dim3(2, Tn / 128, ZHD), blk, GSMEM>>>(
        h1, wqkvT, qkv, nullptr, nullptr,
        192, Dn, Dn, Dn, 192,
        (long long)Tn * Dn, Hn, 0LL, 1,          // A: per batch b = z/H
        0LL, 1, (long long)256 * Dn, Hn,         // B: per head h = z%H (padded)
        (long long)Tn * 192, 1, 0LL, 1);         // C: per z

    // ---- V transpose (rounded): qkv[:, :, 128:192] -> vt [z][HD][T]
    transpose_rna<<<dim3(HDn / 32, Tn / 32, ZHD), tblk>>>(
        qkv + 128, vt, 192, (long long)Tn * 192, Tn, (long long)HDn * Tn);

    // ---- flash attention (tf32) -> att (rounded, concat layout)
    flash_tf32<<<dim3(Tn / 128, ZHD), blk>>>(qkv, vt, att);

    // ---- O projection + bias + residual: x2 = x + att @ Wo + bo
    gemm_tf32<2><<<dim3(Dn / 128, ROWS / 128, 1), blk, GSMEM>>>(
        att, woT, x2, bo, x,
        Dn, Dn, Dn, Dn, Dn,
        0LL, 1, 0LL, 1, 0LL, 1, 0LL, 1, 0LL, 1, 0LL, 1);

    // ---- LN2: x2 -> h2 (rounded)
    ln_kernel<<<ROWS, blk>>>(x2, g2, be2, h2);

    // ---- FFN1: mid = relu(h2 @ W1 + b1) (rounded)
    gemm_tf32<1><<<dim3(4 * Dn / 128, ROWS / 128, 1), blk, GSMEM>>>(
        h2, w1T, mid, b1, nullptr,
        4 * Dn, Dn, Dn, Dn, 4 * Dn,
        0LL, 1, 0LL, 1, 0LL, 1, 0LL, 1, 0LL, 1, 0LL, 1);

    // ---- FFN2: out = x2 + mid @ W2 + b2
    gemm_tf32<2><<<dim3(Dn / 128, ROWS / 128, 1), blk, GSMEM>>>(
        mid, w2T, out, b2, x2,
        Dn, 4 * Dn, 4 * Dn, 4 * Dn, Dn,
        0LL, 1, 0LL, 1, 0LL, 1, 0LL, 1, 0LL, 1, 0LL, 1);
}